// round 1
// baseline (speedup 1.0000x reference)
#include <cuda_runtime.h>
#include <cuda_bf16.h>
#include <math.h>

// Problem constants
#define BB   8
#define NN   4096
#define KK   16
#define DD   128
#define LL   2
#define NCLS 40
#define BN   (BB*NN)          // 32768
#define MBIG (BN*KK)          // 524288

// ---------------- scratch (device globals; no allocation allowed) -----------
__device__ float g_x[BN*DD];
__device__ float g_q[BN*DD];
__device__ float g_k[BN*DD];
__device__ float g_v[BN*DD];
__device__ float g_agg[BN*DD];
__device__ int   g_idx[MBIG];
__device__ float g_rel[MBIG*3];
__device__ float g_delta[(size_t)MBIG*DD];
__device__ float g_h2[(size_t)MBIG*DD];
__device__ float g_logits[(size_t)MBIG*DD];
__device__ float g_pmax[BB*32*DD];

// ---------------- embedding: x = relu(features @ W_embed) -------------------
__global__ void embed_k(const float* __restrict__ f, const float* __restrict__ W) {
    int m = blockIdx.x;          // 0..BN-1
    int d = threadIdx.x;         // 0..127
    float f0 = f[m*3+0], f1 = f[m*3+1], f2 = f[m*3+2];
    float v = f0*W[d] + f1*W[DD+d] + f2*W[2*DD+d];
    g_x[m*DD + d] = fmaxf(v, 0.f);
}

// ---------------- kNN (top-16 smallest d2, incl self) + rel -----------------
#define TJ 1024
__global__ __launch_bounds__(256) void knn_k(const float* __restrict__ pos) {
    int b = blockIdx.y;
    int i = blockIdx.x*256 + threadIdx.x;     // query index within batch
    const float* pb = pos + (size_t)b*NN*3;
    float px = pb[i*3+0], py = pb[i*3+1], pz = pb[i*3+2];
    float sqi = px*px + py*py + pz*pz;

    float bd[KK]; int bi[KK];
#pragma unroll
    for (int t = 0; t < KK; t++) { bd[t] = 3.4e38f; bi[t] = -1; }
    float worst = 3.4e38f; int wslot = 0;

    __shared__ float sp[TJ*3];
    __shared__ float ssq[TJ];

    for (int j0 = 0; j0 < NN; j0 += TJ) {
        for (int t = threadIdx.x; t < TJ; t += 256) {
            float a = pb[(j0+t)*3+0];
            float c1 = pb[(j0+t)*3+1];
            float c2 = pb[(j0+t)*3+2];
            sp[t*3+0] = a; sp[t*3+1] = c1; sp[t*3+2] = c2;
            ssq[t] = a*a + c1*c1 + c2*c2;
        }
        __syncthreads();
        for (int jj = 0; jj < TJ; jj++) {
            float dot = px*sp[jj*3] + py*sp[jj*3+1] + pz*sp[jj*3+2];
            float d2 = sqi + ssq[jj] - 2.0f*dot;
            if (d2 < worst) {
                bd[wslot] = d2; bi[wslot] = j0 + jj;
                worst = bd[0]; wslot = 0;
#pragma unroll
                for (int t = 1; t < KK; t++)
                    if (bd[t] > worst) { worst = bd[t]; wslot = t; }
            }
        }
        __syncthreads();
    }
    int base = (b*NN + i)*KK;
#pragma unroll
    for (int t = 0; t < KK; t++) {
        int j = bi[t];
        g_idx[base + t] = j;
        g_rel[(size_t)(base+t)*3+0] = px - pb[j*3+0];
        g_rel[(size_t)(base+t)*3+1] = py - pb[j*3+1];
        g_rel[(size_t)(base+t)*3+2] = pz - pb[j*3+2];
    }
}

// ---------------- generic fp32 GEMM: C[M,128] = act(A[M,128] @ W[128,128]) --
// MODE 0: none; 1: relu; 2: residual add (C = Res + A@W)
template<int MODE>
__global__ __launch_bounds__(256) void gemm128(const float* __restrict__ A,
                                               const float* __restrict__ W,
                                               float* __restrict__ C,
                                               const float* __restrict__ Res) {
    __shared__ float As[16][132];
    __shared__ float Ws[16][128];
    int t = threadIdx.x;
    int mBase = blockIdx.x * 128;
    int tx = t & 15, ty = t >> 4;
    float acc[8][8] = {};

    for (int k0 = 0; k0 < 128; k0 += 16) {
#pragma unroll
        for (int i = 0; i < 2; i++) {
            int lin = t + i*256;
            int m = lin >> 2, kq = lin & 3;
            float4 a = *(const float4*)(A + (size_t)(mBase+m)*128 + k0 + kq*4);
            As[kq*4+0][m] = a.x; As[kq*4+1][m] = a.y;
            As[kq*4+2][m] = a.z; As[kq*4+3][m] = a.w;
        }
#pragma unroll
        for (int i = 0; i < 2; i++) {
            int lin = t + i*256;
            int k = lin >> 5, nq = lin & 31;
            *(float4*)&Ws[k][nq*4] = *(const float4*)(W + (k0+k)*128 + nq*4);
        }
        __syncthreads();
#pragma unroll
        for (int kk = 0; kk < 16; kk++) {
            float4 a0 = *(const float4*)&As[kk][ty*8];
            float4 a1 = *(const float4*)&As[kk][ty*8+4];
            float4 b0 = *(const float4*)&Ws[kk][tx*8];
            float4 b1 = *(const float4*)&Ws[kk][tx*8+4];
            float av[8] = {a0.x,a0.y,a0.z,a0.w,a1.x,a1.y,a1.z,a1.w};
            float bv[8] = {b0.x,b0.y,b0.z,b0.w,b1.x,b1.y,b1.z,b1.w};
#pragma unroll
            for (int i = 0; i < 8; i++)
#pragma unroll
                for (int j = 0; j < 8; j++)
                    acc[i][j] += av[i]*bv[j];
        }
        __syncthreads();
    }
#pragma unroll
    for (int i = 0; i < 8; i++) {
        size_t row = (size_t)(mBase + ty*8 + i) * 128 + tx*8;
#pragma unroll
        for (int j = 0; j < 8; j += 4) {
            float4 c;
            c.x = acc[i][j+0]; c.y = acc[i][j+1]; c.z = acc[i][j+2]; c.w = acc[i][j+3];
            if (MODE == 1) {
                c.x = fmaxf(c.x,0.f); c.y = fmaxf(c.y,0.f);
                c.z = fmaxf(c.z,0.f); c.w = fmaxf(c.w,0.f);
            }
            if (MODE == 2) {
                float4 r = *(const float4*)(Res + row + j);
                c.x += r.x; c.y += r.y; c.z += r.z; c.w += r.w;
            }
            *(float4*)(C + row + j) = c;
        }
    }
}

// ---------------- delta = relu(rel @ P1) @ P2, A generated on the fly -------
__global__ __launch_bounds__(256) void delta_gemm(const float* __restrict__ P1,
                                                  const float* __restrict__ P2) {
    __shared__ float As[16][132];
    __shared__ float Ws[16][128];
    __shared__ float relS[128][3];
    __shared__ float P1s[3][128];
    int t = threadIdx.x;
    int mBase = blockIdx.x * 128;
    int tx = t & 15, ty = t >> 4;
    if (t < 128) {
        relS[t][0] = g_rel[(size_t)(mBase+t)*3+0];
        relS[t][1] = g_rel[(size_t)(mBase+t)*3+1];
        relS[t][2] = g_rel[(size_t)(mBase+t)*3+2];
    }
    for (int i = t; i < 384; i += 256) P1s[i/128][i%128] = P1[i];
    __syncthreads();

    float acc[8][8] = {};
    for (int k0 = 0; k0 < 128; k0 += 16) {
#pragma unroll
        for (int i = 0; i < 2; i++) {
            int lin = t + i*256;
            int m = lin >> 2, kq = lin & 3;
            float r0 = relS[m][0], r1 = relS[m][1], r2 = relS[m][2];
#pragma unroll
            for (int cc = 0; cc < 4; cc++) {
                int c = k0 + kq*4 + cc;
                float v = r0*P1s[0][c] + r1*P1s[1][c] + r2*P1s[2][c];
                As[kq*4+cc][m] = fmaxf(v, 0.f);
            }
        }
#pragma unroll
        for (int i = 0; i < 2; i++) {
            int lin = t + i*256;
            int k = lin >> 5, nq = lin & 31;
            *(float4*)&Ws[k][nq*4] = *(const float4*)(P2 + (k0+k)*128 + nq*4);
        }
        __syncthreads();
#pragma unroll
        for (int kk = 0; kk < 16; kk++) {
            float4 a0 = *(const float4*)&As[kk][ty*8];
            float4 a1 = *(const float4*)&As[kk][ty*8+4];
            float4 b0 = *(const float4*)&Ws[kk][tx*8];
            float4 b1 = *(const float4*)&Ws[kk][tx*8+4];
            float av[8] = {a0.x,a0.y,a0.z,a0.w,a1.x,a1.y,a1.z,a1.w};
            float bv[8] = {b0.x,b0.y,b0.z,b0.w,b1.x,b1.y,b1.z,b1.w};
#pragma unroll
            for (int i = 0; i < 8; i++)
#pragma unroll
                for (int j = 0; j < 8; j++)
                    acc[i][j] += av[i]*bv[j];
        }
        __syncthreads();
    }
#pragma unroll
    for (int i = 0; i < 8; i++) {
        size_t row = (size_t)(mBase + ty*8 + i) * 128 + tx*8;
#pragma unroll
        for (int j = 0; j < 8; j += 4) {
            float4 c;
            c.x = acc[i][j+0]; c.y = acc[i][j+1]; c.z = acc[i][j+2]; c.w = acc[i][j+3];
            *(float4*)(g_delta + row + j) = c;
        }
    }
}

// ---------------- h2 = relu((q - k_gather + delta) @ G1), A generated -------
__global__ __launch_bounds__(256) void ggemm(const float* __restrict__ G1) {
    __shared__ float As[16][132];
    __shared__ float Ws[16][128];
    __shared__ int rowK[128];
    __shared__ int rowQ[128];
    int t = threadIdx.x;
    int mBase = blockIdx.x * 128;
    int tx = t & 15, ty = t >> 4;
    if (t < 128) {
        int m = mBase + t;
        int bn = m >> 4;               // point index
        int b  = bn >> 12;             // batch (N=4096)
        int j  = g_idx[m];
        rowK[t] = b*NN + j;
        rowQ[t] = bn;
    }
    __syncthreads();

    float acc[8][8] = {};
    for (int k0 = 0; k0 < 128; k0 += 16) {
#pragma unroll
        for (int i = 0; i < 2; i++) {
            int lin = t + i*256;
            int m = lin >> 2, kq = lin & 3;
            int off = k0 + kq*4;
            float4 dl = *(const float4*)(g_delta + (size_t)(mBase+m)*128 + off);
            float4 qv = *(const float4*)(g_q + (size_t)rowQ[m]*128 + off);
            float4 kv = *(const float4*)(g_k + (size_t)rowK[m]*128 + off);
            As[kq*4+0][m] = qv.x - kv.x + dl.x;
            As[kq*4+1][m] = qv.y - kv.y + dl.y;
            As[kq*4+2][m] = qv.z - kv.z + dl.z;
            As[kq*4+3][m] = qv.w - kv.w + dl.w;
        }
#pragma unroll
        for (int i = 0; i < 2; i++) {
            int lin = t + i*256;
            int k = lin >> 5, nq = lin & 31;
            *(float4*)&Ws[k][nq*4] = *(const float4*)(G1 + (k0+k)*128 + nq*4);
        }
        __syncthreads();
#pragma unroll
        for (int kk = 0; kk < 16; kk++) {
            float4 a0 = *(const float4*)&As[kk][ty*8];
            float4 a1 = *(const float4*)&As[kk][ty*8+4];
            float4 b0 = *(const float4*)&Ws[kk][tx*8];
            float4 b1 = *(const float4*)&Ws[kk][tx*8+4];
            float av[8] = {a0.x,a0.y,a0.z,a0.w,a1.x,a1.y,a1.z,a1.w};
            float bv[8] = {b0.x,b0.y,b0.z,b0.w,b1.x,b1.y,b1.z,b1.w};
#pragma unroll
            for (int i = 0; i < 8; i++)
#pragma unroll
                for (int j = 0; j < 8; j++)
                    acc[i][j] += av[i]*bv[j];
        }
        __syncthreads();
    }
#pragma unroll
    for (int i = 0; i < 8; i++) {
        size_t row = (size_t)(mBase + ty*8 + i) * 128 + tx*8;
#pragma unroll
        for (int j = 0; j < 8; j += 4) {
            float4 c;
            c.x = fmaxf(acc[i][j+0],0.f); c.y = fmaxf(acc[i][j+1],0.f);
            c.z = fmaxf(acc[i][j+2],0.f); c.w = fmaxf(acc[i][j+3],0.f);
            *(float4*)(g_h2 + row + j) = c;
        }
    }
}

// ---------------- softmax over K (per feature) + aggregate ------------------
__global__ void softagg_k() {
    int bn = blockIdx.x;
    int d  = threadIdx.x;
    int b  = bn >> 12;
    size_t base = (size_t)bn * KK * DD + d;

    __shared__ int rows[KK];
    if (d < KK) rows[d] = b*NN + g_idx[bn*KK + d];
    __syncthreads();

    float lo[KK];
    float mx = -3.4e38f;
#pragma unroll
    for (int k = 0; k < KK; k++) {
        lo[k] = g_logits[base + (size_t)k*DD];
        mx = fmaxf(mx, lo[k]);
    }
    float s = 0.f;
#pragma unroll
    for (int k = 0; k < KK; k++) { lo[k] = expf(lo[k] - mx); s += lo[k]; }
    float inv = 1.f / s;
    float a = 0.f;
#pragma unroll
    for (int k = 0; k < KK; k++) {
        float vj = g_v[(size_t)rows[k]*DD + d];
        float dl = g_delta[base + (size_t)k*DD];
        a += lo[k]*inv*(vj + dl);
    }
    g_agg[(size_t)bn*DD + d] = a;
}

// ---------------- global max pool (partial) ---------------------------------
__global__ void poolmax_k() {
    int b  = blockIdx.x >> 5;
    int ch = blockIdx.x & 31;
    int d  = threadIdx.x;
    float m = -3.4e38f;
    for (int n = ch*128; n < ch*128 + 128; n++)
        m = fmaxf(m, g_x[((size_t)b*NN + n)*DD + d]);
    g_pmax[(size_t)blockIdx.x*DD + d] = m;
}

// ---------------- classifier head -------------------------------------------
__global__ void cls_k(const float* __restrict__ Wc1, const float* __restrict__ Wc2,
                      float* __restrict__ out) {
    int b = blockIdx.x;
    int d = threadIdx.x;
    __shared__ float pooled[DD];
    __shared__ float h[DD];
    float m = -3.4e38f;
    for (int ch = 0; ch < 32; ch++)
        m = fmaxf(m, g_pmax[((size_t)b*32 + ch)*DD + d]);
    pooled[d] = m;
    __syncthreads();
    float acc = 0.f;
    for (int c = 0; c < DD; c++) acc += pooled[c]*Wc1[c*DD + d];
    h[d] = fmaxf(acc, 0.f);
    __syncthreads();
    if (d < NCLS) {
        float o = 0.f;
        for (int c = 0; c < DD; c++) o += h[c]*Wc2[c*NCLS + d];
        out[b*NCLS + d] = o;
    }
}

// ---------------- launch -----------------------------------------------------
extern "C" void kernel_launch(void* const* d_in, const int* in_sizes, int n_in,
                              void* d_out, int out_size) {
    const float* features = (const float*)d_in[0];
    const float* pos      = (const float*)d_in[1];
    const float* W_embed  = (const float*)d_in[2];
    const float* Wq       = (const float*)d_in[3];
    const float* Wk       = (const float*)d_in[4];
    const float* Wv       = (const float*)d_in[5];
    const float* P1       = (const float*)d_in[6];
    const float* P2       = (const float*)d_in[7];
    const float* G1       = (const float*)d_in[8];
    const float* G2       = (const float*)d_in[9];
    const float* Wo       = (const float*)d_in[10];
    const float* Wc1      = (const float*)d_in[11];
    const float* Wc2      = (const float*)d_in[12];
    float* out = (float*)d_out;

    static float *px=nullptr, *pq=nullptr, *pk=nullptr, *pv=nullptr,
                 *pagg=nullptr, *ph2=nullptr, *plog=nullptr;
    if (!px) {
        cudaGetSymbolAddress((void**)&px,   g_x);
        cudaGetSymbolAddress((void**)&pq,   g_q);
        cudaGetSymbolAddress((void**)&pk,   g_k);
        cudaGetSymbolAddress((void**)&pv,   g_v);
        cudaGetSymbolAddress((void**)&pagg, g_agg);
        cudaGetSymbolAddress((void**)&ph2,  g_h2);
        cudaGetSymbolAddress((void**)&plog, g_logits);
    }

    embed_k<<<BN, DD>>>(features, W_embed);
    knn_k<<<dim3(NN/256, BB), 256>>>(pos);

    for (int l = 0; l < LL; l++) {
        const float* WqL = Wq + (size_t)l*DD*DD;
        const float* WkL = Wk + (size_t)l*DD*DD;
        const float* WvL = Wv + (size_t)l*DD*DD;
        const float* P1L = P1 + (size_t)l*3*DD;
        const float* P2L = P2 + (size_t)l*DD*DD;
        const float* G1L = G1 + (size_t)l*DD*DD;
        const float* G2L = G2 + (size_t)l*DD*DD;
        const float* WoL = Wo + (size_t)l*DD*DD;

        gemm128<0><<<BN/128, 256>>>(px, WqL, pq, nullptr);
        gemm128<0><<<BN/128, 256>>>(px, WkL, pk, nullptr);
        gemm128<0><<<BN/128, 256>>>(px, WvL, pv, nullptr);
        delta_gemm<<<MBIG/128, 256>>>(P1L, P2L);
        ggemm<<<MBIG/128, 256>>>(G1L);
        gemm128<0><<<MBIG/128, 256>>>(ph2, G2L, plog, nullptr);
        softagg_k<<<BN, DD>>>();
        gemm128<2><<<BN/128, 256>>>(pagg, WoL, px, px);
    }

    poolmax_k<<<BB*32, DD>>>();
    cls_k<<<BB, DD>>>(Wc1, Wc2, out);
}

// round 3
// speedup vs baseline: 1.0734x; 1.0734x over previous
#include <cuda_runtime.h>
#include <cstdint>
#include <math.h>

// Problem constants
#define BB   8
#define NN   4096
#define KK   16
#define DD   128
#define LL   2
#define NCLS 40
#define BN   (BB*NN)          // 32768
#define MBIG (BN*KK)          // 524288

// ---------------- scratch (device globals; no allocation allowed) -----------
__device__ float g_x[BN*DD];
__device__ float g_q[BN*DD];
__device__ float g_k[BN*DD];
__device__ float g_v[BN*DD];
__device__ float g_agg[BN*DD];
__device__ int   g_idx[MBIG];
__device__ float g_rel[MBIG*3];
__device__ float g_delta[(size_t)MBIG*DD];
__device__ float g_h2[(size_t)MBIG*DD];
__device__ float g_pmax[BB*32*DD];

// ---------------- tf32 helpers (sm_80+ PTX, no 'a'-arch features) -----------
__device__ __forceinline__ uint32_t f2tf(float f) {
    uint32_t u; asm("cvt.rna.tf32.f32 %0, %1;" : "=r"(u) : "f"(f)); return u;
}
__device__ __forceinline__ float tff(float f) { return __uint_as_float(f2tf(f)); }

__device__ __forceinline__ void mma8(float* d, const uint32_t* a, const uint32_t* b) {
    asm volatile(
        "mma.sync.aligned.m16n8k8.row.col.f32.tf32.tf32.f32 "
        "{%0,%1,%2,%3}, {%4,%5,%6,%7}, {%8,%9}, {%0,%1,%2,%3};"
        : "+f"(d[0]), "+f"(d[1]), "+f"(d[2]), "+f"(d[3])
        : "r"(a[0]), "r"(a[1]), "r"(a[2]), "r"(a[3]), "r"(b[0]), "r"(b[1]));
}

#define SA 132                    // A smem stride (floats)
#define SB 136                    // B smem stride (floats)
#define MG_SMEM ((128*SA + 128*SB) * 4)   // 137216 bytes

// ======================= tf32 mma GEMM: C[M,128] = epi(A @ W) ===============
// ASRC: 0 = load A from Aptr; 1 = relu(rel@P1); 2 = q - k_gather + delta
// CEPI: 0 = none; 1 = relu; 2 = C = Res + acc
template<int ASRC, int CEPI>
__global__ __launch_bounds__(256) void mgemm(const float* __restrict__ A,
                                             const float* __restrict__ W,
                                             float* __restrict__ C,
                                             const float* __restrict__ Res,
                                             const float* __restrict__ P1L) {
    extern __shared__ float sm[];
    float* As = sm;               // [128][SA]
    float* Bs = sm + 128*SA;      // [128][SB]
    __shared__ int rowQ[128], rowK[128];
    __shared__ float relS[128][3];
    __shared__ float P1s[3][128];

    int t = threadIdx.x;
    int mBase = blockIdx.x * 128;

    if (ASRC == 2 && t < 128) {
        int m = mBase + t;
        int bn = m >> 4;
        rowQ[t] = bn;
        rowK[t] = (bn >> 12) * NN + g_idx[m];
    }
    if (ASRC == 1) {
        if (t < 128) {
            relS[t][0] = g_rel[(size_t)(mBase+t)*3+0];
            relS[t][1] = g_rel[(size_t)(mBase+t)*3+1];
            relS[t][2] = g_rel[(size_t)(mBase+t)*3+2];
        }
        for (int i = t; i < 384; i += 256) P1s[i/128][i%128] = P1L[i];
    }
    if (ASRC != 0) __syncthreads();

    // ---- B: weight [k][n] row-major == .col operand; tf32-round on copy ----
    for (int i = t; i < 4096; i += 256) {
        int k = i >> 5, c4 = i & 31;
        float4 v = *(const float4*)(W + k*128 + c4*4);
        float* d = &Bs[k*SB + c4*4];
        d[0] = tff(v.x); d[1] = tff(v.y); d[2] = tff(v.z); d[3] = tff(v.w);
    }
    // ---- A tile build ----
    for (int i = t; i < 4096; i += 256) {
        int row = i >> 5, c4 = i & 31;
        int c = c4*4;
        float4 v;
        if (ASRC == 0) {
            v = *(const float4*)(A + (size_t)(mBase+row)*128 + c);
        } else if (ASRC == 1) {
            float r0 = relS[row][0], r1 = relS[row][1], r2 = relS[row][2];
            v.x = fmaxf(r0*P1s[0][c+0] + r1*P1s[1][c+0] + r2*P1s[2][c+0], 0.f);
            v.y = fmaxf(r0*P1s[0][c+1] + r1*P1s[1][c+1] + r2*P1s[2][c+1], 0.f);
            v.z = fmaxf(r0*P1s[0][c+2] + r1*P1s[1][c+2] + r2*P1s[2][c+2], 0.f);
            v.w = fmaxf(r0*P1s[0][c+3] + r1*P1s[1][c+3] + r2*P1s[2][c+3], 0.f);
        } else {
            float4 qv = *(const float4*)(g_q + (size_t)rowQ[row]*128 + c);
            float4 kv = *(const float4*)(g_k + (size_t)rowK[row]*128 + c);
            float4 dl = *(const float4*)(g_delta + (size_t)(mBase+row)*128 + c);
            v.x = qv.x - kv.x + dl.x;
            v.y = qv.y - kv.y + dl.y;
            v.z = qv.z - kv.z + dl.z;
            v.w = qv.w - kv.w + dl.w;
        }
        float* d = &As[row*SA + c];
        d[0] = tff(v.x); d[1] = tff(v.y); d[2] = tff(v.z); d[3] = tff(v.w);
    }
    __syncthreads();

    // ---- mma mainloop: warp grid 2x4, each warp 64x32 ----
    int lane = t & 31, wid = t >> 5;
    int r0 = (wid & 1) * 64, c0 = (wid >> 1) * 32;
    int ar = lane >> 2, ak = lane & 3;
    const uint32_t* Au = (const uint32_t*)As;
    const uint32_t* Bu = (const uint32_t*)Bs;
    float acc[4][4][4] = {};

    for (int k0 = 0; k0 < 128; k0 += 8) {
        uint32_t af[4][4], bf[4][2];
#pragma unroll
        for (int mf = 0; mf < 4; mf++) {
            int r = r0 + mf*16 + ar;
            af[mf][0] = Au[r*SA + k0 + ak];
            af[mf][1] = Au[(r+8)*SA + k0 + ak];
            af[mf][2] = Au[r*SA + k0 + ak + 4];
            af[mf][3] = Au[(r+8)*SA + k0 + ak + 4];
        }
#pragma unroll
        for (int nf = 0; nf < 4; nf++) {
            int cc = c0 + nf*8 + ar;
            bf[nf][0] = Bu[(k0+ak)*SB + cc];
            bf[nf][1] = Bu[(k0+ak+4)*SB + cc];
        }
#pragma unroll
        for (int mf = 0; mf < 4; mf++)
#pragma unroll
            for (int nf = 0; nf < 4; nf++)
                mma8(acc[mf][nf], af[mf], bf[nf]);
    }

    // ---- epilogue ----
#pragma unroll
    for (int mf = 0; mf < 4; mf++)
#pragma unroll
    for (int nf = 0; nf < 4; nf++) {
        int r = mBase + r0 + mf*16 + ar;
        int c = c0 + nf*8 + 2*ak;
        float2 v0 = make_float2(acc[mf][nf][0], acc[mf][nf][1]);
        float2 v1 = make_float2(acc[mf][nf][2], acc[mf][nf][3]);
        if (CEPI == 1) {
            v0.x = fmaxf(v0.x,0.f); v0.y = fmaxf(v0.y,0.f);
            v1.x = fmaxf(v1.x,0.f); v1.y = fmaxf(v1.y,0.f);
        }
        if (CEPI == 2) {
            float2 a0 = *(const float2*)(Res + (size_t)r*128 + c);
            float2 a1 = *(const float2*)(Res + (size_t)(r+8)*128 + c);
            v0.x += a0.x; v0.y += a0.y; v1.x += a1.x; v1.y += a1.y;
        }
        *(float2*)(C + (size_t)r*128 + c) = v0;
        *(float2*)(C + (size_t)(r+8)*128 + c) = v1;
    }
}

// ============ fused: logits = h2@G2 -> softmax over K -> aggregate ==========
__global__ __launch_bounds__(256) void glsoft(const float* __restrict__ H2,
                                              const float* __restrict__ G2) {
    extern __shared__ float sm[];
    float* As = sm;
    float* Bs = sm + 128*SA;
    __shared__ int rowV[128];

    int t = threadIdx.x;
    int mBase = blockIdx.x * 128;

    if (t < 128) {
        int m = mBase + t;
        rowV[t] = ((m >> 4) >> 12) * NN + g_idx[m];
    }

    for (int i = t; i < 4096; i += 256) {
        int k = i >> 5, c4 = i & 31;
        float4 v = *(const float4*)(G2 + k*128 + c4*4);
        float* d = &Bs[k*SB + c4*4];
        d[0] = tff(v.x); d[1] = tff(v.y); d[2] = tff(v.z); d[3] = tff(v.w);
    }
    for (int i = t; i < 4096; i += 256) {
        int row = i >> 5, c4 = i & 31;
        float4 v = *(const float4*)(H2 + (size_t)(mBase+row)*128 + c4*4);
        float* d = &As[row*SA + c4*4];
        d[0] = tff(v.x); d[1] = tff(v.y); d[2] = tff(v.z); d[3] = tff(v.w);
    }
    __syncthreads();

    int lane = t & 31, wid = t >> 5;
    int r0 = (wid & 1) * 64, c0 = (wid >> 1) * 32;
    int ar = lane >> 2, ak = lane & 3;
    const uint32_t* Au = (const uint32_t*)As;
    const uint32_t* Bu = (const uint32_t*)Bs;
    float acc[4][4][4] = {};

    for (int k0 = 0; k0 < 128; k0 += 8) {
        uint32_t af[4][4], bf[4][2];
#pragma unroll
        for (int mf = 0; mf < 4; mf++) {
            int r = r0 + mf*16 + ar;
            af[mf][0] = Au[r*SA + k0 + ak];
            af[mf][1] = Au[(r+8)*SA + k0 + ak];
            af[mf][2] = Au[r*SA + k0 + ak + 4];
            af[mf][3] = Au[(r+8)*SA + k0 + ak + 4];
        }
#pragma unroll
        for (int nf = 0; nf < 4; nf++) {
            int cc = c0 + nf*8 + ar;
            bf[nf][0] = Bu[(k0+ak)*SB + cc];
            bf[nf][1] = Bu[(k0+ak+4)*SB + cc];
        }
#pragma unroll
        for (int mf = 0; mf < 4; mf++)
#pragma unroll
            for (int nf = 0; nf < 4; nf++)
                mma8(acc[mf][nf], af[mf], bf[nf]);
    }
    __syncthreads();            // everyone done reading As

    // logits -> smem (reuse As)
#pragma unroll
    for (int mf = 0; mf < 4; mf++)
#pragma unroll
    for (int nf = 0; nf < 4; nf++) {
        int r = r0 + mf*16 + ar;
        int c = c0 + nf*8 + 2*ak;
        As[r*SA + c]     = acc[mf][nf][0];
        As[r*SA + c+1]   = acc[mf][nf][1];
        As[(r+8)*SA + c]   = acc[mf][nf][2];
        As[(r+8)*SA + c+1] = acc[mf][nf][3];
    }
    __syncthreads();

    // softmax over K (per feature) + aggregate: 8 points x 128 dims
    for (int it = t; it < 1024; it += 256) {
        int p = it >> 7, d = it & 127;
        float lo[KK];
        float mx = -3.4e38f;
#pragma unroll
        for (int k = 0; k < KK; k++) {
            lo[k] = As[(p*16 + k)*SA + d];
            mx = fmaxf(mx, lo[k]);
        }
        float s = 0.f;
#pragma unroll
        for (int k = 0; k < KK; k++) { lo[k] = expf(lo[k] - mx); s += lo[k]; }
        float inv = 1.f / s;
        float a = 0.f;
#pragma unroll
        for (int k = 0; k < KK; k++) {
            float vj = g_v[(size_t)rowV[p*16+k]*128 + d];
            float dl = g_delta[(size_t)(mBase + p*16 + k)*128 + d];
            a += lo[k]*inv*(vj + dl);
        }
        g_agg[(size_t)((mBase >> 4) + p)*128 + d] = a;
    }
}

// ---------------- embedding: x = relu(features @ W_embed) -------------------
__global__ void embed_k(const float* __restrict__ f, const float* __restrict__ W) {
    int m = blockIdx.x;
    int d = threadIdx.x;
    float f0 = f[m*3+0], f1 = f[m*3+1], f2 = f[m*3+2];
    float v = f0*W[d] + f1*W[DD+d] + f2*W[2*DD+d];
    g_x[m*DD + d] = fmaxf(v, 0.f);
}

// ---------------- kNN (top-16 smallest d2, incl self) + rel -----------------
#define TJ 1024
__global__ __launch_bounds__(256) void knn_k(const float* __restrict__ pos) {
    int b = blockIdx.y;
    int i = blockIdx.x*256 + threadIdx.x;
    const float* pb = pos + (size_t)b*NN*3;
    float px = pb[i*3+0], py = pb[i*3+1], pz = pb[i*3+2];
    float sqi = px*px + py*py + pz*pz;

    float bd[KK]; int bi[KK];
#pragma unroll
    for (int t = 0; t < KK; t++) { bd[t] = 3.4e38f; bi[t] = -1; }
    float worst = 3.4e38f; int wslot = 0;

    __shared__ float sp[TJ*3];
    __shared__ float ssq[TJ];

    for (int j0 = 0; j0 < NN; j0 += TJ) {
        for (int t = threadIdx.x; t < TJ; t += 256) {
            float a = pb[(j0+t)*3+0];
            float c1 = pb[(j0+t)*3+1];
            float c2 = pb[(j0+t)*3+2];
            sp[t*3+0] = a; sp[t*3+1] = c1; sp[t*3+2] = c2;
            ssq[t] = a*a + c1*c1 + c2*c2;
        }
        __syncthreads();
        for (int jj = 0; jj < TJ; jj++) {
            float dot = px*sp[jj*3] + py*sp[jj*3+1] + pz*sp[jj*3+2];
            float d2 = sqi + ssq[jj] - 2.0f*dot;
            if (d2 < worst) {
                bd[wslot] = d2; bi[wslot] = j0 + jj;
                worst = bd[0]; wslot = 0;
#pragma unroll
                for (int t = 1; t < KK; t++)
                    if (bd[t] > worst) { worst = bd[t]; wslot = t; }
            }
        }
        __syncthreads();
    }
    int base = (b*NN + i)*KK;
#pragma unroll
    for (int t = 0; t < KK; t++) {
        int j = bi[t];
        g_idx[base + t] = j;
        g_rel[(size_t)(base+t)*3+0] = px - pb[j*3+0];
        g_rel[(size_t)(base+t)*3+1] = py - pb[j*3+1];
        g_rel[(size_t)(base+t)*3+2] = pz - pb[j*3+2];
    }
}

// ---------------- global max pool (partial) ---------------------------------
__global__ void poolmax_k() {
    int b  = blockIdx.x >> 5;
    int ch = blockIdx.x & 31;
    int d  = threadIdx.x;
    float m = -3.4e38f;
    for (int n = ch*128; n < ch*128 + 128; n++)
        m = fmaxf(m, g_x[((size_t)b*NN + n)*DD + d]);
    g_pmax[(size_t)blockIdx.x*DD + d] = m;
}

// ---------------- classifier head -------------------------------------------
__global__ void cls_k(const float* __restrict__ Wc1, const float* __restrict__ Wc2,
                      float* __restrict__ out) {
    int b = blockIdx.x;
    int d = threadIdx.x;
    __shared__ float pooled[DD];
    __shared__ float h[DD];
    float m = -3.4e38f;
    for (int ch = 0; ch < 32; ch++)
        m = fmaxf(m, g_pmax[((size_t)b*32 + ch)*DD + d]);
    pooled[d] = m;
    __syncthreads();
    float acc = 0.f;
    for (int c = 0; c < DD; c++) acc += pooled[c]*Wc1[c*DD + d];
    h[d] = fmaxf(acc, 0.f);
    __syncthreads();
    if (d < NCLS) {
        float o = 0.f;
        for (int c = 0; c < DD; c++) o += h[c]*Wc2[c*NCLS + d];
        out[b*NCLS + d] = o;
    }
}

// ---------------- launch -----------------------------------------------------
extern "C" void kernel_launch(void* const* d_in, const int* in_sizes, int n_in,
                              void* d_out, int out_size) {
    const float* features = (const float*)d_in[0];
    const float* pos      = (const float*)d_in[1];
    const float* W_embed  = (const float*)d_in[2];
    const float* Wq       = (const float*)d_in[3];
    const float* Wk       = (const float*)d_in[4];
    const float* Wv       = (const float*)d_in[5];
    const float* P1       = (const float*)d_in[6];
    const float* P2       = (const float*)d_in[7];
    const float* G1       = (const float*)d_in[8];
    const float* G2       = (const float*)d_in[9];
    const float* Wo       = (const float*)d_in[10];
    const float* Wc1      = (const float*)d_in[11];
    const float* Wc2      = (const float*)d_in[12];
    float* out = (float*)d_out;

    static float *px=nullptr, *pq=nullptr, *pk=nullptr, *pv=nullptr,
                 *pagg=nullptr, *ph2=nullptr, *pdelta=nullptr;
    if (!px) {
        cudaGetSymbolAddress((void**)&px,    g_x);
        cudaGetSymbolAddress((void**)&pq,    g_q);
        cudaGetSymbolAddress((void**)&pk,    g_k);
        cudaGetSymbolAddress((void**)&pv,    g_v);
        cudaGetSymbolAddress((void**)&pagg,  g_agg);
        cudaGetSymbolAddress((void**)&ph2,   g_h2);
        cudaGetSymbolAddress((void**)&pdelta,g_delta);
        cudaFuncSetAttribute(mgemm<0,0>, cudaFuncAttributeMaxDynamicSharedMemorySize, MG_SMEM);
        cudaFuncSetAttribute(mgemm<0,2>, cudaFuncAttributeMaxDynamicSharedMemorySize, MG_SMEM);
        cudaFuncSetAttribute(mgemm<1,0>, cudaFuncAttributeMaxDynamicSharedMemorySize, MG_SMEM);
        cudaFuncSetAttribute(mgemm<2,1>, cudaFuncAttributeMaxDynamicSharedMemorySize, MG_SMEM);
        cudaFuncSetAttribute(glsoft,     cudaFuncAttributeMaxDynamicSharedMemorySize, MG_SMEM);
    }

    embed_k<<<BN, DD>>>(features, W_embed);
    knn_k<<<dim3(NN/256, BB), 256>>>(pos);

    for (int l = 0; l < LL; l++) {
        const float* WqL = Wq + (size_t)l*DD*DD;
        const float* WkL = Wk + (size_t)l*DD*DD;
        const float* WvL = Wv + (size_t)l*DD*DD;
        const float* P1L = P1 + (size_t)l*3*DD;
        const float* P2L = P2 + (size_t)l*DD*DD;
        const float* G1L = G1 + (size_t)l*DD*DD;
        const float* G2L = G2 + (size_t)l*DD*DD;
        const float* WoL = Wo + (size_t)l*DD*DD;

        mgemm<0,0><<<BN/128, 256, MG_SMEM>>>(px, WqL, pq, nullptr, nullptr);
        mgemm<0,0><<<BN/128, 256, MG_SMEM>>>(px, WkL, pk, nullptr, nullptr);
        mgemm<0,0><<<BN/128, 256, MG_SMEM>>>(px, WvL, pv, nullptr, nullptr);
        mgemm<1,0><<<MBIG/128, 256, MG_SMEM>>>(nullptr, P2L, pdelta, nullptr, P1L);
        mgemm<2,1><<<MBIG/128, 256, MG_SMEM>>>(nullptr, G1L, ph2, nullptr, nullptr);
        glsoft<<<MBIG/128, 256, MG_SMEM>>>(ph2, G2L);
        mgemm<0,2><<<BN/128, 256, MG_SMEM>>>(pagg, WoL, px, px, nullptr);
    }

    poolmax_k<<<BB*32, DD>>>();
    cls_k<<<BB, DD>>>(Wc1, Wc2, out);
}

// round 4
// speedup vs baseline: 2.0817x; 1.9394x over previous
#include <cuda_runtime.h>
#include <cstdint>
#include <math.h>

// Problem constants
#define BB   8
#define NN   4096
#define KK   16
#define DD   128
#define LL   2
#define NCLS 40
#define BN   (BB*NN)          // 32768
#define MBIG (BN*KK)          // 524288

// ---------------- scratch (device globals; no allocation allowed) -----------
__device__ float g_x[BN*DD];
__device__ float g_q[BN*DD];
__device__ float g_k[BN*DD];
__device__ float g_v[BN*DD];
__device__ float g_agg[BN*DD];
__device__ int   g_idx[MBIG];
__device__ float g_rel[MBIG*3];
__device__ float g_delta[(size_t)MBIG*DD];
__device__ float g_h2[(size_t)MBIG*DD];
__device__ float g_pmax[BB*32*DD];

// ---------------- helpers (sm_80-level PTX only) -----------------------------
__device__ __forceinline__ uint32_t f2tf(float f) {
    uint32_t u; asm("cvt.rna.tf32.f32 %0, %1;" : "=r"(u) : "f"(f)); return u;
}
__device__ __forceinline__ float tff(float f) { return __uint_as_float(f2tf(f)); }

__device__ __forceinline__ void mma8(float* d, const uint32_t* a, const uint32_t* b) {
    asm volatile(
        "mma.sync.aligned.m16n8k8.row.col.f32.tf32.tf32.f32 "
        "{%0,%1,%2,%3}, {%4,%5,%6,%7}, {%8,%9}, {%0,%1,%2,%3};"
        : "+f"(d[0]), "+f"(d[1]), "+f"(d[2]), "+f"(d[3])
        : "r"(a[0]), "r"(a[1]), "r"(a[2]), "r"(a[3]), "r"(b[0]), "r"(b[1]));
}
__device__ __forceinline__ uint32_t smem_u32(const void* p) {
    uint32_t a;
    asm("{ .reg .u64 t; cvta.to.shared.u64 t, %1; cvt.u32.u64 %0, t; }" : "=r"(a) : "l"(p));
    return a;
}
__device__ __forceinline__ void cpa16(uint32_t dst, const void* src) {
    asm volatile("cp.async.ca.shared.global [%0], [%1], 16;" :: "r"(dst), "l"(src));
}
__device__ __forceinline__ void cpa_commit() {
    asm volatile("cp.async.commit_group;" ::: "memory");
}
template<int N> __device__ __forceinline__ void cpa_wait() {
    asm volatile("cp.async.wait_group %0;" :: "n"(N) : "memory");
}

// ---------------- pipelined tile geometry ------------------------------------
#define SAc  36                     // A chunk stride (floats): conflict-free frags
#define SBc  136                    // B chunk stride (floats)
#define ABUF (128*SAc)              // 4608 floats
#define BBUF (32*SBc)               // 4352 floats
#define STAGE (ABUF + BBUF)         // 8960 floats
#define PIPE_SMEM (2*STAGE*4)       // 71680 bytes
#define SL   132                    // logits stage stride (glsoft)

// load one k-chunk (32 wide) into stage buffers
// ASRC: 0 = cp.async from A; 1 = relu(rel@P1); 2 = q - k_gather + delta
template<int ASRC>
__device__ __forceinline__ void load_chunk(
    int k0, float* As, float* Bs,
    const float* __restrict__ A, const float* __restrict__ W,
    int mBase, int t,
    const int* rowQ, const int* rowK,
    const float (*relS)[3], const float (*P1s)[128])
{
    uint32_t bsm = smem_u32(Bs);
#pragma unroll
    for (int i = 0; i < 4; i++) {
        int idx = t + i*256;
        int k = idx >> 5, q = idx & 31;
        cpa16(bsm + (uint32_t)(k*SBc + q*4)*4u, W + (size_t)(k0+k)*128 + q*4);
    }
    if (ASRC == 0) {
        uint32_t asmb = smem_u32(As);
#pragma unroll
        for (int i = 0; i < 4; i++) {
            int idx = t + i*256;
            int row = idx >> 3, q = idx & 7;
            cpa16(asmb + (uint32_t)(row*SAc + q*4)*4u,
                  A + (size_t)(mBase+row)*128 + k0 + q*4);
        }
    } else if (ASRC == 1) {
#pragma unroll
        for (int i = 0; i < 4; i++) {
            int idx = t + i*256;
            int row = idx >> 3, q = idx & 7;
            int c = k0 + q*4;
            float r0 = relS[row][0], r1 = relS[row][1], r2 = relS[row][2];
            float* d = &As[row*SAc + q*4];
            d[0] = tff(fmaxf(r0*P1s[0][c+0] + r1*P1s[1][c+0] + r2*P1s[2][c+0], 0.f));
            d[1] = tff(fmaxf(r0*P1s[0][c+1] + r1*P1s[1][c+1] + r2*P1s[2][c+1], 0.f));
            d[2] = tff(fmaxf(r0*P1s[0][c+2] + r1*P1s[1][c+2] + r2*P1s[2][c+2], 0.f));
            d[3] = tff(fmaxf(r0*P1s[0][c+3] + r1*P1s[1][c+3] + r2*P1s[2][c+3], 0.f));
        }
    } else {
#pragma unroll
        for (int i = 0; i < 4; i++) {
            int idx = t + i*256;
            int row = idx >> 3, q = idx & 7;
            int c = k0 + q*4;
            float4 qv = *(const float4*)(g_q + (size_t)rowQ[row]*128 + c);
            float4 kv = *(const float4*)(g_k + (size_t)rowK[row]*128 + c);
            float4 dl = *(const float4*)(g_delta + (size_t)(mBase+row)*128 + c);
            float* d = &As[row*SAc + q*4];
            d[0] = tff(qv.x - kv.x + dl.x);
            d[1] = tff(qv.y - kv.y + dl.y);
            d[2] = tff(qv.z - kv.z + dl.z);
            d[3] = tff(qv.w - kv.w + dl.w);
        }
    }
}

// MMAs over one 32-wide chunk
__device__ __forceinline__ void mma_chunk(const float* As, const float* Bs,
                                          int r0, int c0, int ar, int ak,
                                          float acc[4][4][4]) {
    const uint32_t* Au = (const uint32_t*)As;
    const uint32_t* Bu = (const uint32_t*)Bs;
#pragma unroll
    for (int kk = 0; kk < 32; kk += 8) {
        uint32_t af[4][4], bf[4][2];
#pragma unroll
        for (int mf = 0; mf < 4; mf++) {
            int r = r0 + mf*16 + ar;
            af[mf][0] = Au[r*SAc + kk + ak];
            af[mf][1] = Au[(r+8)*SAc + kk + ak];
            af[mf][2] = Au[r*SAc + kk + ak + 4];
            af[mf][3] = Au[(r+8)*SAc + kk + ak + 4];
        }
#pragma unroll
        for (int nf = 0; nf < 4; nf++) {
            int cc = c0 + nf*8 + ar;
            bf[nf][0] = Bu[(kk+ak)*SBc + cc];
            bf[nf][1] = Bu[(kk+ak+4)*SBc + cc];
        }
#pragma unroll
        for (int mf = 0; mf < 4; mf++)
#pragma unroll
            for (int nf = 0; nf < 4; nf++)
                mma8(acc[mf][nf], af[mf], bf[nf]);
    }
}

// ======================= pipelined tf32 GEMM: C = epi(A @ W) ================
// CEPI: 0 none; 1 relu; 2 C = Res + acc
template<int ASRC, int CEPI>
__global__ __launch_bounds__(256, 2) void mgemm(const float* __restrict__ A,
                                                const float* __restrict__ W,
                                                float* __restrict__ C,
                                                const float* __restrict__ Res,
                                                const float* __restrict__ P1L) {
    extern __shared__ float sm[];
    float* Abuf[2] = { sm, sm + STAGE };
    float* Bbuf[2] = { sm + ABUF, sm + STAGE + ABUF };
    __shared__ int rowQ[128], rowK[128];
    __shared__ float relS[128][3];
    __shared__ float P1s[3][128];

    int t = threadIdx.x;
    int mBase = blockIdx.x * 128;

    if (ASRC == 2 && t < 128) {
        int m = mBase + t;
        int bn = m >> 4;
        rowQ[t] = bn;
        rowK[t] = (bn >> 12) * NN + g_idx[m];
    }
    if (ASRC == 1) {
        if (t < 128) {
            relS[t][0] = g_rel[(size_t)(mBase+t)*3+0];
            relS[t][1] = g_rel[(size_t)(mBase+t)*3+1];
            relS[t][2] = g_rel[(size_t)(mBase+t)*3+2];
        }
        for (int i = t; i < 384; i += 256) P1s[i/128][i%128] = P1L[i];
    }
    if (ASRC != 0) __syncthreads();

    int lane = t & 31, wid = t >> 5;
    int r0 = (wid & 1) * 64, c0 = (wid >> 1) * 32;
    int ar = lane >> 2, ak = lane & 3;
    float acc[4][4][4] = {};

    load_chunk<ASRC>(0, Abuf[0], Bbuf[0], A, W, mBase, t, rowQ, rowK, relS, P1s);
    cpa_commit();

#pragma unroll
    for (int c = 0; c < 4; c++) {
        if (c < 3) {
            load_chunk<ASRC>((c+1)*32, Abuf[(c+1)&1], Bbuf[(c+1)&1],
                             A, W, mBase, t, rowQ, rowK, relS, P1s);
            cpa_commit();
            cpa_wait<1>();
        } else {
            cpa_wait<0>();
        }
        __syncthreads();
        mma_chunk(Abuf[c&1], Bbuf[c&1], r0, c0, ar, ak, acc);
        __syncthreads();
    }

    // ---- epilogue ----
#pragma unroll
    for (int mf = 0; mf < 4; mf++)
#pragma unroll
    for (int nf = 0; nf < 4; nf++) {
        int r = mBase + r0 + mf*16 + ar;
        int c = c0 + nf*8 + 2*ak;
        float2 v0 = make_float2(acc[mf][nf][0], acc[mf][nf][1]);
        float2 v1 = make_float2(acc[mf][nf][2], acc[mf][nf][3]);
        if (CEPI == 1) {
            v0.x = fmaxf(v0.x,0.f); v0.y = fmaxf(v0.y,0.f);
            v1.x = fmaxf(v1.x,0.f); v1.y = fmaxf(v1.y,0.f);
        }
        if (CEPI == 2) {
            float2 a0 = *(const float2*)(Res + (size_t)r*128 + c);
            float2 a1 = *(const float2*)(Res + (size_t)(r+8)*128 + c);
            v0.x += a0.x; v0.y += a0.y; v1.x += a1.x; v1.y += a1.y;
        }
        *(float2*)(C + (size_t)r*128 + c) = v0;
        *(float2*)(C + (size_t)(r+8)*128 + c) = v1;
    }
}

// ============ fused: logits = h2@G2 -> softmax over K -> aggregate ==========
__global__ __launch_bounds__(256, 2) void glsoft(const float* __restrict__ H2,
                                                 const float* __restrict__ G2) {
    extern __shared__ float sm[];
    float* Abuf[2] = { sm, sm + STAGE };
    float* Bbuf[2] = { sm + ABUF, sm + STAGE + ABUF };
    __shared__ int rowV[128];

    int t = threadIdx.x;
    int mBase = blockIdx.x * 128;

    if (t < 128) {
        int m = mBase + t;
        rowV[t] = ((m >> 4) >> 12) * NN + g_idx[m];
    }

    int lane = t & 31, wid = t >> 5;
    int r0 = (wid & 1) * 64, c0 = (wid >> 1) * 32;
    int ar = lane >> 2, ak = lane & 3;
    float acc[4][4][4] = {};

    load_chunk<0>(0, Abuf[0], Bbuf[0], H2, G2, mBase, t, nullptr, nullptr, nullptr, nullptr);
    cpa_commit();

#pragma unroll
    for (int c = 0; c < 4; c++) {
        if (c < 3) {
            load_chunk<0>((c+1)*32, Abuf[(c+1)&1], Bbuf[(c+1)&1],
                          H2, G2, mBase, t, nullptr, nullptr, nullptr, nullptr);
            cpa_commit();
            cpa_wait<1>();
        } else {
            cpa_wait<0>();
        }
        __syncthreads();
        mma_chunk(Abuf[c&1], Bbuf[c&1], r0, c0, ar, ak, acc);
        __syncthreads();
    }

    // logits -> smem (alias pipeline buffers, stride SL)
    float* Ls = sm;
#pragma unroll
    for (int mf = 0; mf < 4; mf++)
#pragma unroll
    for (int nf = 0; nf < 4; nf++) {
        int r = r0 + mf*16 + ar;
        int c = c0 + nf*8 + 2*ak;
        Ls[r*SL + c]       = acc[mf][nf][0];
        Ls[r*SL + c+1]     = acc[mf][nf][1];
        Ls[(r+8)*SL + c]   = acc[mf][nf][2];
        Ls[(r+8)*SL + c+1] = acc[mf][nf][3];
    }
    __syncthreads();

    // softmax over K (per feature) + aggregate: 8 points x 128 dims
    for (int it = t; it < 1024; it += 256) {
        int p = it >> 7, d = it & 127;
        float lo[KK];
        float mx = -3.4e38f;
#pragma unroll
        for (int k = 0; k < KK; k++) {
            lo[k] = Ls[(p*16 + k)*SL + d];
            mx = fmaxf(mx, lo[k]);
        }
        float s = 0.f;
#pragma unroll
        for (int k = 0; k < KK; k++) { lo[k] = expf(lo[k] - mx); s += lo[k]; }
        float inv = 1.f / s;
        float a = 0.f;
#pragma unroll
        for (int k = 0; k < KK; k++) {
            float vj = g_v[(size_t)rowV[p*16+k]*128 + d];
            float dl = g_delta[(size_t)(mBase + p*16 + k)*128 + d];
            a += lo[k]*inv*(vj + dl);
        }
        g_agg[(size_t)((mBase >> 4) + p)*128 + d] = a;
    }
}

// ---------------- embedding: x = relu(features @ W_embed) -------------------
__global__ void embed_k(const float* __restrict__ f, const float* __restrict__ W) {
    int m = blockIdx.x;
    int d = threadIdx.x;
    float f0 = f[m*3+0], f1 = f[m*3+1], f2 = f[m*3+2];
    float v = f0*W[d] + f1*W[DD+d] + f2*W[2*DD+d];
    g_x[m*DD + d] = fmaxf(v, 0.f);
}

// ---------------- kNN (top-16 smallest d2, incl self) + rel -----------------
#define TJ 1024
__global__ __launch_bounds__(256) void knn_k(const float* __restrict__ pos) {
    int b = blockIdx.y;
    int i = blockIdx.x*256 + threadIdx.x;
    const float* pb = pos + (size_t)b*NN*3;
    float px = pb[i*3+0], py = pb[i*3+1], pz = pb[i*3+2];
    float sqi = px*px + py*py + pz*pz;

    float bd[KK]; int bi[KK];
#pragma unroll
    for (int t = 0; t < KK; t++) { bd[t] = 3.4e38f; bi[t] = -1; }
    float worst = 3.4e38f; int wslot = 0;

    __shared__ float sp[TJ*3];
    __shared__ float ssq[TJ];

    for (int j0 = 0; j0 < NN; j0 += TJ) {
        for (int t = threadIdx.x; t < TJ; t += 256) {
            float a = pb[(j0+t)*3+0];
            float c1 = pb[(j0+t)*3+1];
            float c2 = pb[(j0+t)*3+2];
            sp[t*3+0] = a; sp[t*3+1] = c1; sp[t*3+2] = c2;
            ssq[t] = a*a + c1*c1 + c2*c2;
        }
        __syncthreads();
        for (int jj = 0; jj < TJ; jj++) {
            float dot = px*sp[jj*3] + py*sp[jj*3+1] + pz*sp[jj*3+2];
            float d2 = sqi + ssq[jj] - 2.0f*dot;
            if (d2 < worst) {
                bd[wslot] = d2; bi[wslot] = j0 + jj;
                worst = bd[0]; wslot = 0;
#pragma unroll
                for (int t = 1; t < KK; t++)
                    if (bd[t] > worst) { worst = bd[t]; wslot = t; }
            }
        }
        __syncthreads();
    }
    int base = (b*NN + i)*KK;
#pragma unroll
    for (int t = 0; t < KK; t++) {
        int j = bi[t];
        g_idx[base + t] = j;
        g_rel[(size_t)(base+t)*3+0] = px - pb[j*3+0];
        g_rel[(size_t)(base+t)*3+1] = py - pb[j*3+1];
        g_rel[(size_t)(base+t)*3+2] = pz - pb[j*3+2];
    }
}

// ---------------- global max pool (partial) ---------------------------------
__global__ void poolmax_k() {
    int b  = blockIdx.x >> 5;
    int ch = blockIdx.x & 31;
    int d  = threadIdx.x;
    float m = -3.4e38f;
    for (int n = ch*128; n < ch*128 + 128; n++)
        m = fmaxf(m, g_x[((size_t)b*NN + n)*DD + d]);
    g_pmax[(size_t)blockIdx.x*DD + d] = m;
}

// ---------------- classifier head -------------------------------------------
__global__ void cls_k(const float* __restrict__ Wc1, const float* __restrict__ Wc2,
                      float* __restrict__ out) {
    int b = blockIdx.x;
    int d = threadIdx.x;
    __shared__ float pooled[DD];
    __shared__ float h[DD];
    float m = -3.4e38f;
    for (int ch = 0; ch < 32; ch++)
        m = fmaxf(m, g_pmax[((size_t)b*32 + ch)*DD + d]);
    pooled[d] = m;
    __syncthreads();
    float acc = 0.f;
    for (int c = 0; c < DD; c++) acc += pooled[c]*Wc1[c*DD + d];
    h[d] = fmaxf(acc, 0.f);
    __syncthreads();
    if (d < NCLS) {
        float o = 0.f;
        for (int c = 0; c < DD; c++) o += h[c]*Wc2[c*NCLS + d];
        out[b*NCLS + d] = o;
    }
}

// ---------------- launch -----------------------------------------------------
extern "C" void kernel_launch(void* const* d_in, const int* in_sizes, int n_in,
                              void* d_out, int out_size) {
    const float* features = (const float*)d_in[0];
    const float* pos      = (const float*)d_in[1];
    const float* W_embed  = (const float*)d_in[2];
    const float* Wq       = (const float*)d_in[3];
    const float* Wk       = (const float*)d_in[4];
    const float* Wv       = (const float*)d_in[5];
    const float* P1       = (const float*)d_in[6];
    const float* P2       = (const float*)d_in[7];
    const float* G1       = (const float*)d_in[8];
    const float* G2       = (const float*)d_in[9];
    const float* Wo       = (const float*)d_in[10];
    const float* Wc1      = (const float*)d_in[11];
    const float* Wc2      = (const float*)d_in[12];
    float* out = (float*)d_out;

    static float *px=nullptr, *pq=nullptr, *pk=nullptr, *pv=nullptr,
                 *pagg=nullptr, *ph2=nullptr, *pdelta=nullptr;
    if (!px) {
        cudaGetSymbolAddress((void**)&px,    g_x);
        cudaGetSymbolAddress((void**)&pq,    g_q);
        cudaGetSymbolAddress((void**)&pk,    g_k);
        cudaGetSymbolAddress((void**)&pv,    g_v);
        cudaGetSymbolAddress((void**)&pagg,  g_agg);
        cudaGetSymbolAddress((void**)&ph2,   g_h2);
        cudaGetSymbolAddress((void**)&pdelta,g_delta);
        cudaFuncSetAttribute(mgemm<0,0>, cudaFuncAttributeMaxDynamicSharedMemorySize, PIPE_SMEM);
        cudaFuncSetAttribute(mgemm<0,2>, cudaFuncAttributeMaxDynamicSharedMemorySize, PIPE_SMEM);
        cudaFuncSetAttribute(mgemm<1,0>, cudaFuncAttributeMaxDynamicSharedMemorySize, PIPE_SMEM);
        cudaFuncSetAttribute(mgemm<2,1>, cudaFuncAttributeMaxDynamicSharedMemorySize, PIPE_SMEM);
        cudaFuncSetAttribute(glsoft,     cudaFuncAttributeMaxDynamicSharedMemorySize, PIPE_SMEM);
    }

    embed_k<<<BN, DD>>>(features, W_embed);
    knn_k<<<dim3(NN/256, BB), 256>>>(pos);

    for (int l = 0; l < LL; l++) {
        const float* WqL = Wq + (size_t)l*DD*DD;
        const float* WkL = Wk + (size_t)l*DD*DD;
        const float* WvL = Wv + (size_t)l*DD*DD;
        const float* P1L = P1 + (size_t)l*3*DD;
        const float* P2L = P2 + (size_t)l*DD*DD;
        const float* G1L = G1 + (size_t)l*DD*DD;
        const float* G2L = G2 + (size_t)l*DD*DD;
        const float* WoL = Wo + (size_t)l*DD*DD;

        mgemm<0,0><<<BN/128, 256, PIPE_SMEM>>>(px, WqL, pq, nullptr, nullptr);
        mgemm<0,0><<<BN/128, 256, PIPE_SMEM>>>(px, WkL, pk, nullptr, nullptr);
        mgemm<0,0><<<BN/128, 256, PIPE_SMEM>>>(px, WvL, pv, nullptr, nullptr);
        mgemm<1,0><<<MBIG/128, 256, PIPE_SMEM>>>(nullptr, P2L, pdelta, nullptr, P1L);
        mgemm<2,1><<<MBIG/128, 256, PIPE_SMEM>>>(nullptr, G1L, ph2, nullptr, nullptr);
        glsoft<<<MBIG/128, 256, PIPE_SMEM>>>(ph2, G2L);
        mgemm<0,2><<<BN/128, 256, PIPE_SMEM>>>(pagg, WoL, px, px, nullptr);
    }

    poolmax_k<<<BB*32, DD>>>();
    cls_k<<<BB, DD>>>(Wc1, Wc2, out);
}

// round 5
// speedup vs baseline: 2.5235x; 1.2122x over previous
#include <cuda_runtime.h>
#include <cuda_fp16.h>
#include <cstdint>
#include <math.h>

// Problem constants
#define BB   8
#define NN   4096
#define KK   16
#define DD   128
#define LL   2
#define NCLS 40
#define BN   (BB*NN)          // 32768
#define MBIG (BN*KK)          // 524288

// ---------------- scratch (device globals; no allocation allowed) -----------
__device__ float  g_x[BN*DD];                 // fp32 residual stream
__device__ __half g_xh[BN*DD];                // fp16 mirror of x (GEMM A operand)
__device__ __half g_q[BN*DD];
__device__ __half g_k[BN*DD];
__device__ __half g_v[BN*DD];
__device__ __half g_agg[BN*DD];
__device__ int    g_idx[MBIG];
__device__ float  g_rel[MBIG*3];
__device__ float  g_pmax[BB*32*DD];
__device__ __half g_wimg[14*DD*DD];           // fp16 weight images, [n][k] per slot

// ---------------- helpers ----------------------------------------------------
__device__ __forceinline__ uint32_t h2u(__half2 h) { return *(uint32_t*)&h; }
__device__ __forceinline__ uint32_t smem_u32(const void* p) {
    uint32_t a;
    asm("{ .reg .u64 t; cvta.to.shared.u64 t, %1; cvt.u32.u64 %0, t; }" : "=r"(a) : "l"(p));
    return a;
}
__device__ __forceinline__ void cpa16(uint32_t dst, const void* src) {
    asm volatile("cp.async.ca.shared.global [%0], [%1], 16;" :: "r"(dst), "l"(src));
}
__device__ __forceinline__ void cpa_commit() {
    asm volatile("cp.async.commit_group;" ::: "memory");
}
template<int N> __device__ __forceinline__ void cpa_wait() {
    asm volatile("cp.async.wait_group %0;" :: "n"(N) : "memory");
}
__device__ __forceinline__ void mma16(float* d, const uint32_t* a, const uint32_t* b) {
    asm volatile(
        "mma.sync.aligned.m16n8k16.row.col.f32.f16.f16.f32 "
        "{%0,%1,%2,%3}, {%4,%5,%6,%7}, {%8,%9}, {%0,%1,%2,%3};"
        : "+f"(d[0]), "+f"(d[1]), "+f"(d[2]), "+f"(d[3])
        : "r"(a[0]), "r"(a[1]), "r"(a[2]), "r"(a[3]), "r"(b[0]), "r"(b[1]));
}

// MMA over one 64-half K chunk. A: b32 array, row stride sA, k base kb (b32).
// B: stage-local b32 array, row stride 36 (n-major). Warp tile 64x32.
__device__ __forceinline__ void mma_chunk16(const uint32_t* __restrict__ Au, int sA, int kb,
                                            const uint32_t* __restrict__ Bu,
                                            int r0, int c0, int ar, int ak,
                                            float acc[4][4][4]) {
#pragma unroll
    for (int ks = 0; ks < 4; ks++) {
        int ka = kb + ks*8;
        uint32_t af[4][4], bf[4][2];
#pragma unroll
        for (int mf = 0; mf < 4; mf++) {
            int r = r0 + mf*16 + ar;
            af[mf][0] = Au[r*sA + ka + ak];
            af[mf][1] = Au[(r+8)*sA + ka + ak];
            af[mf][2] = Au[r*sA + ka + ak + 4];
            af[mf][3] = Au[(r+8)*sA + ka + ak + 4];
        }
#pragma unroll
        for (int nf = 0; nf < 4; nf++) {
            int cc = c0 + nf*8 + ar;
            bf[nf][0] = Bu[cc*36 + ks*8 + ak];
            bf[nf][1] = Bu[cc*36 + ks*8 + ak + 4];
        }
#pragma unroll
        for (int mf = 0; mf < 4; mf++)
#pragma unroll
            for (int nf = 0; nf < 4; nf++)
                mma16(acc[mf][nf], af[mf], bf[nf]);
    }
}

// B stage loader: Bimg [n=128][k=128] fp16, chunk k0 (halves), stage stride 72 halves
__device__ __forceinline__ void loadB(uint32_t bsm, const __half* __restrict__ Bimg,
                                      int k0, int t) {
#pragma unroll
    for (int i = 0; i < 4; i++) {
        int idx = t + i*256;
        int n = idx >> 3, seg = idx & 7;
        cpa16(bsm + (uint32_t)(n*144 + seg*16), Bimg + (size_t)n*128 + k0 + seg*8);
    }
}
// A stage loader from fp16 global [m][128]
__device__ __forceinline__ void loadA(uint32_t asmb, const __half* __restrict__ A,
                                      int mBase, int k0, int t) {
#pragma unroll
    for (int i = 0; i < 4; i++) {
        int idx = t + i*256;
        int row = idx >> 3, seg = idx & 7;
        cpa16(asmb + (uint32_t)(row*144 + seg*16), A + (size_t)(mBase+row)*128 + k0 + seg*8);
    }
}

// ---------------- weight image prep: img[n][k] = (half)W[k][n] ---------------
__global__ void prep_w(const float* __restrict__ src, __half* __restrict__ dst) {
    int n = blockIdx.x, k = threadIdx.x;
    dst[n*128 + k] = __float2half(src[k*128 + n]);
}

// ======================= small fp16 GEMM: 128xN tiles =======================
// CEPI 0: Ch = (half)acc.   CEPI 2: Cf = Res + acc (fp32), Ch = (half)Cf.
#define HG_SMEM (4*4608*4)    // 73728 B : Ast[2] + Bst[2], each 128x36 b32
template<int CEPI>
__global__ __launch_bounds__(256, 2) void hgemm(const __half* __restrict__ A,
                                                const __half* __restrict__ Bimg,
                                                __half* __restrict__ Ch,
                                                float* __restrict__ Cf,
                                                const float* __restrict__ Res) {
    extern __shared__ float sm[];
    uint32_t* Ast[2] = { (uint32_t*)sm, (uint32_t*)sm + 4608 };
    uint32_t* Bst[2] = { (uint32_t*)sm + 9216, (uint32_t*)sm + 13824 };
    int t = threadIdx.x;
    int mBase = blockIdx.x * 128;

    loadA(smem_u32(Ast[0]), A, mBase, 0, t);
    loadB(smem_u32(Bst[0]), Bimg, 0, t);
    cpa_commit();
    loadA(smem_u32(Ast[1]), A, mBase, 64, t);
    loadB(smem_u32(Bst[1]), Bimg, 64, t);
    cpa_commit();

    int lane = t & 31, wid = t >> 5;
    int r0 = (wid & 1) * 64, c0 = (wid >> 1) * 32;
    int ar = lane >> 2, ak = lane & 3;
    float acc[4][4][4] = {};

    cpa_wait<1>(); __syncthreads();
    mma_chunk16(Ast[0], 36, 0, Bst[0], r0, c0, ar, ak, acc);
    cpa_wait<0>(); __syncthreads();
    mma_chunk16(Ast[1], 36, 0, Bst[1], r0, c0, ar, ak, acc);

#pragma unroll
    for (int mf = 0; mf < 4; mf++)
#pragma unroll
    for (int nf = 0; nf < 4; nf++) {
        int r = mBase + r0 + mf*16 + ar;
        int c = c0 + nf*8 + 2*ak;
        float2 v0 = make_float2(acc[mf][nf][0], acc[mf][nf][1]);
        float2 v1 = make_float2(acc[mf][nf][2], acc[mf][nf][3]);
        if (CEPI == 2) {
            float2 a0 = *(const float2*)(Res + (size_t)r*128 + c);
            float2 a1 = *(const float2*)(Res + (size_t)(r+8)*128 + c);
            v0.x += a0.x; v0.y += a0.y; v1.x += a1.x; v1.y += a1.y;
            *(float2*)(Cf + (size_t)r*128 + c) = v0;
            *(float2*)(Cf + (size_t)(r+8)*128 + c) = v1;
        }
        *(__half2*)(Ch + (size_t)r*128 + c) = __floats2half2_rn(v0.x, v0.y);
        *(__half2*)(Ch + (size_t)(r+8)*128 + c) = __floats2half2_rn(v1.x, v1.y);
    }
}

// ======== fused per-neighbor block: delta -> g -> h2 -> logits -> agg =======
// smem (floats): Dl[128*132] @0 | H(b32)[128*68] @16896 | Ast0 @25600 Ast1 @30208
//                | Bst0 @34816 Bst1 @39424   (total 44032 floats = 176128 B)
// Ls (fp32 logits, 128x132) aliases @25600.
#define FU_SMEM (44032*4)
__global__ __launch_bounds__(256, 1) void pt_fused(const float* __restrict__ P1L,
                                                   const __half* __restrict__ P2img,
                                                   const __half* __restrict__ G1img,
                                                   const __half* __restrict__ G2img) {
    extern __shared__ float sm[];
    float*    Dl = sm;
    uint32_t* Hu = (uint32_t*)(sm + 16896);
    uint32_t* Ast[2] = { (uint32_t*)(sm + 25600), (uint32_t*)(sm + 30208) };
    uint32_t* Bst[2] = { (uint32_t*)(sm + 34816), (uint32_t*)(sm + 39424) };
    float*    Ls = sm + 25600;

    __shared__ int   rowK[128];
    __shared__ float relS[128][3];
    __shared__ float P1s[3][128];

    int t = threadIdx.x;
    int mBase = blockIdx.x * 128;
    int lane = t & 31, wid = t >> 5;
    int r0 = (wid & 1) * 64, c0 = (wid >> 1) * 32;
    int ar = lane >> 2, ak = lane & 3;

    if (t < 128) {
        int m = mBase + t;
        rowK[t] = ((m >> 4) >> 12) * NN + g_idx[m];
        relS[t][0] = g_rel[(size_t)m*3+0];
        relS[t][1] = g_rel[(size_t)m*3+1];
        relS[t][2] = g_rel[(size_t)m*3+2];
    }
    for (int i = t; i < 384; i += 256) P1s[i/128][i%128] = P1L[i];
    __syncthreads();

    float acc[4][4][4] = {};

    // ================= GEMM1: delta = relu(rel@P1) @ P2 -> Dl (fp32) ========
    // build A chunk: 4096 b32 per chunk, 16 per thread
    {
        loadB(smem_u32(Bst[0]), P2img, 0, t);  cpa_commit();
        loadB(smem_u32(Bst[1]), P2img, 64, t); cpa_commit();
#pragma unroll
        for (int st = 0; st < 2; st++) {
            int k0 = st*64;
#pragma unroll
            for (int i = 0; i < 16; i++) {
                int idx = t + i*256;
                int row = idx >> 5, j = idx & 31;
                int c = k0 + 2*j;
                float a0 = relS[row][0], a1 = relS[row][1], a2 = relS[row][2];
                float v0 = fmaxf(a0*P1s[0][c]   + a1*P1s[1][c]   + a2*P1s[2][c],   0.f);
                float v1 = fmaxf(a0*P1s[0][c+1] + a1*P1s[1][c+1] + a2*P1s[2][c+1], 0.f);
                Ast[st][row*36 + j] = h2u(__floats2half2_rn(v0, v1));
            }
        }
        cpa_wait<1>(); __syncthreads();
        mma_chunk16(Ast[0], 36, 0, Bst[0], r0, c0, ar, ak, acc);
        cpa_wait<0>(); __syncthreads();
        mma_chunk16(Ast[1], 36, 0, Bst[1], r0, c0, ar, ak, acc);
        __syncthreads();
#pragma unroll
        for (int mf = 0; mf < 4; mf++)
#pragma unroll
        for (int nf = 0; nf < 4; nf++) {
            int r = r0 + mf*16 + ar;
            int c = c0 + nf*8 + 2*ak;
            Dl[r*132 + c]     = acc[mf][nf][0];
            Dl[r*132 + c+1]   = acc[mf][nf][1];
            Dl[(r+8)*132 + c]   = acc[mf][nf][2];
            Dl[(r+8)*132 + c+1] = acc[mf][nf][3];
            acc[mf][nf][0] = acc[mf][nf][1] = acc[mf][nf][2] = acc[mf][nf][3] = 0.f;
        }
        __syncthreads();
    }

    // ================= GEMM2: h2 = relu((q - k_g + delta) @ G1) -> Hu =======
    {
        loadB(smem_u32(Bst[0]), G1img, 0, t);  cpa_commit();
        loadB(smem_u32(Bst[1]), G1img, 64, t); cpa_commit();
#pragma unroll
        for (int st = 0; st < 2; st++) {
            int k0 = st*64;
#pragma unroll
            for (int i = 0; i < 16; i++) {
                int idx = t + i*256;
                int row = idx >> 5, j = idx & 31;
                int c = k0 + 2*j;
                int bn = (mBase + row) >> 4;
                __half2 qh = *(const __half2*)(g_q + (size_t)bn*128 + c);
                __half2 kh = *(const __half2*)(g_k + (size_t)rowK[row]*128 + c);
                float v0 = __half2float(qh.x) - __half2float(kh.x) + Dl[row*132 + c];
                float v1 = __half2float(qh.y) - __half2float(kh.y) + Dl[row*132 + c + 1];
                Ast[st][row*36 + j] = h2u(__floats2half2_rn(v0, v1));
            }
        }
        cpa_wait<1>(); __syncthreads();
        mma_chunk16(Ast[0], 36, 0, Bst[0], r0, c0, ar, ak, acc);
        cpa_wait<0>(); __syncthreads();
        mma_chunk16(Ast[1], 36, 0, Bst[1], r0, c0, ar, ak, acc);
        __syncthreads();
#pragma unroll
        for (int mf = 0; mf < 4; mf++)
#pragma unroll
        for (int nf = 0; nf < 4; nf++) {
            int r = r0 + mf*16 + ar;
            int cb = (c0 + nf*8) >> 1;
            Hu[r*68 + cb + ak] = h2u(__floats2half2_rn(
                fmaxf(acc[mf][nf][0], 0.f), fmaxf(acc[mf][nf][1], 0.f)));
            Hu[(r+8)*68 + cb + ak] = h2u(__floats2half2_rn(
                fmaxf(acc[mf][nf][2], 0.f), fmaxf(acc[mf][nf][3], 0.f)));
            acc[mf][nf][0] = acc[mf][nf][1] = acc[mf][nf][2] = acc[mf][nf][3] = 0.f;
        }
        __syncthreads();
    }

    // ================= GEMM3: logits = h2 @ G2 ==============================
    {
        loadB(smem_u32(Bst[0]), G2img, 0, t);  cpa_commit();
        loadB(smem_u32(Bst[1]), G2img, 64, t); cpa_commit();
        cpa_wait<1>(); __syncthreads();
        mma_chunk16(Hu, 68, 0,  Bst[0], r0, c0, ar, ak, acc);
        cpa_wait<0>(); __syncthreads();
        mma_chunk16(Hu, 68, 32, Bst[1], r0, c0, ar, ak, acc);
        __syncthreads();      // Bst/Ast dead -> reuse as Ls
#pragma unroll
        for (int mf = 0; mf < 4; mf++)
#pragma unroll
        for (int nf = 0; nf < 4; nf++) {
            int r = r0 + mf*16 + ar;
            int c = c0 + nf*8 + 2*ak;
            Ls[r*132 + c]       = acc[mf][nf][0];
            Ls[r*132 + c+1]     = acc[mf][nf][1];
            Ls[(r+8)*132 + c]   = acc[mf][nf][2];
            Ls[(r+8)*132 + c+1] = acc[mf][nf][3];
        }
        __syncthreads();
    }

    // ================= softmax over K + aggregate ===========================
    for (int it = t; it < 1024; it += 256) {
        int p = it >> 7, d = it & 127;
        float lo[KK];
        float mx = -3.4e38f;
#pragma unroll
        for (int k = 0; k < KK; k++) {
            lo[k] = Ls[(p*16 + k)*132 + d];
            mx = fmaxf(mx, lo[k]);
        }
        float s = 0.f;
#pragma unroll
        for (int k = 0; k < KK; k++) { lo[k] = expf(lo[k] - mx); s += lo[k]; }
        float inv = 1.f / s;
        float a = 0.f;
#pragma unroll
        for (int k = 0; k < KK; k++) {
            float vj = __half2float(g_v[(size_t)rowK[p*16+k]*128 + d]);
            float dl = Dl[(p*16 + k)*132 + d];
            a += lo[k]*inv*(vj + dl);
        }
        g_agg[(size_t)((mBase >> 4) + p)*128 + d] = __float2half(a);
    }
}

// ---------------- embedding: x = relu(features @ W_embed) -------------------
__global__ void embed_k(const float* __restrict__ f, const float* __restrict__ W) {
    int m = blockIdx.x;
    int d = threadIdx.x;
    float f0 = f[m*3+0], f1 = f[m*3+1], f2 = f[m*3+2];
    float v = fmaxf(f0*W[d] + f1*W[DD+d] + f2*W[2*DD+d], 0.f);
    g_x[m*DD + d] = v;
    g_xh[m*DD + d] = __float2half(v);
}

// ---------------- kNN (top-16 smallest d2, incl self) + rel -----------------
#define TJ 1024
__global__ __launch_bounds__(256) void knn_k(const float* __restrict__ pos) {
    int b = blockIdx.y;
    int i = blockIdx.x*256 + threadIdx.x;
    const float* pb = pos + (size_t)b*NN*3;
    float px = pb[i*3+0], py = pb[i*3+1], pz = pb[i*3+2];
    float sqi = px*px + py*py + pz*pz;

    float bd[KK]; int bi[KK];
#pragma unroll
    for (int t = 0; t < KK; t++) { bd[t] = 3.4e38f; bi[t] = -1; }
    float worst = 3.4e38f; int wslot = 0;

    __shared__ float sp[TJ*3];
    __shared__ float ssq[TJ];

    for (int j0 = 0; j0 < NN; j0 += TJ) {
        for (int t = threadIdx.x; t < TJ; t += 256) {
            float a = pb[(j0+t)*3+0];
            float c1 = pb[(j0+t)*3+1];
            float c2 = pb[(j0+t)*3+2];
            sp[t*3+0] = a; sp[t*3+1] = c1; sp[t*3+2] = c2;
            ssq[t] = a*a + c1*c1 + c2*c2;
        }
        __syncthreads();
        for (int jj = 0; jj < TJ; jj++) {
            float dot = px*sp[jj*3] + py*sp[jj*3+1] + pz*sp[jj*3+2];
            float d2 = sqi + ssq[jj] - 2.0f*dot;
            if (d2 < worst) {
                bd[wslot] = d2; bi[wslot] = j0 + jj;
                worst = bd[0]; wslot = 0;
#pragma unroll
                for (int t = 1; t < KK; t++)
                    if (bd[t] > worst) { worst = bd[t]; wslot = t; }
            }
        }
        __syncthreads();
    }
    int base = (b*NN + i)*KK;
#pragma unroll
    for (int t = 0; t < KK; t++) {
        int j = bi[t];
        g_idx[base + t] = j;
        g_rel[(size_t)(base+t)*3+0] = px - pb[j*3+0];
        g_rel[(size_t)(base+t)*3+1] = py - pb[j*3+1];
        g_rel[(size_t)(base+t)*3+2] = pz - pb[j*3+2];
    }
}

// ---------------- global max pool (partial) ---------------------------------
__global__ void poolmax_k() {
    int b  = blockIdx.x >> 5;
    int ch = blockIdx.x & 31;
    int d  = threadIdx.x;
    float m = -3.4e38f;
    for (int n = ch*128; n < ch*128 + 128; n++)
        m = fmaxf(m, g_x[((size_t)b*NN + n)*DD + d]);
    g_pmax[(size_t)blockIdx.x*DD + d] = m;
}

// ---------------- classifier head -------------------------------------------
__global__ void cls_k(const float* __restrict__ Wc1, const float* __restrict__ Wc2,
                      float* __restrict__ out) {
    int b = blockIdx.x;
    int d = threadIdx.x;
    __shared__ float pooled[DD];
    __shared__ float h[DD];
    float m = -3.4e38f;
    for (int ch = 0; ch < 32; ch++)
        m = fmaxf(m, g_pmax[((size_t)b*32 + ch)*DD + d]);
    pooled[d] = m;
    __syncthreads();
    float acc = 0.f;
    for (int c = 0; c < DD; c++) acc += pooled[c]*Wc1[c*DD + d];
    h[d] = fmaxf(acc, 0.f);
    __syncthreads();
    if (d < NCLS) {
        float o = 0.f;
        for (int c = 0; c < DD; c++) o += h[c]*Wc2[c*NCLS + d];
        out[b*NCLS + d] = o;
    }
}

// ---------------- launch -----------------------------------------------------
extern "C" void kernel_launch(void* const* d_in, const int* in_sizes, int n_in,
                              void* d_out, int out_size) {
    const float* features = (const float*)d_in[0];
    const float* pos      = (const float*)d_in[1];
    const float* W_embed  = (const float*)d_in[2];
    const float* Wq       = (const float*)d_in[3];
    const float* Wk       = (const float*)d_in[4];
    const float* Wv       = (const float*)d_in[5];
    const float* P1       = (const float*)d_in[6];
    const float* P2       = (const float*)d_in[7];
    const float* G1       = (const float*)d_in[8];
    const float* G2       = (const float*)d_in[9];
    const float* Wo       = (const float*)d_in[10];
    const float* Wc1      = (const float*)d_in[11];
    const float* Wc2      = (const float*)d_in[12];
    float* out = (float*)d_out;

    static float  *px = nullptr;
    static __half *pxh=nullptr, *pq=nullptr, *pk=nullptr, *pv=nullptr,
                  *pagg=nullptr, *pwimg=nullptr;
    if (!px) {
        cudaGetSymbolAddress((void**)&px,   g_x);
        cudaGetSymbolAddress((void**)&pxh,  g_xh);
        cudaGetSymbolAddress((void**)&pq,   g_q);
        cudaGetSymbolAddress((void**)&pk,   g_k);
        cudaGetSymbolAddress((void**)&pv,   g_v);
        cudaGetSymbolAddress((void**)&pagg, g_agg);
        cudaGetSymbolAddress((void**)&pwimg,g_wimg);
        cudaFuncSetAttribute(hgemm<0>, cudaFuncAttributeMaxDynamicSharedMemorySize, HG_SMEM);
        cudaFuncSetAttribute(hgemm<2>, cudaFuncAttributeMaxDynamicSharedMemorySize, HG_SMEM);
        cudaFuncSetAttribute(pt_fused, cudaFuncAttributeMaxDynamicSharedMemorySize, FU_SMEM);
    }

    // weight images: per layer slots {Wq,Wk,Wv,P2,G1,G2,Wo}
    for (int l = 0; l < LL; l++) {
        prep_w<<<128,128>>>(Wq + (size_t)l*DD*DD, pwimg + (size_t)(l*7+0)*16384);
        prep_w<<<128,128>>>(Wk + (size_t)l*DD*DD, pwimg + (size_t)(l*7+1)*16384);
        prep_w<<<128,128>>>(Wv + (size_t)l*DD*DD, pwimg + (size_t)(l*7+2)*16384);
        prep_w<<<128,128>>>(P2 + (size_t)l*DD*DD, pwimg + (size_t)(l*7+3)*16384);
        prep_w<<<128,128>>>(G1 + (size_t)l*DD*DD, pwimg + (size_t)(l*7+4)*16384);
        prep_w<<<128,128>>>(G2 + (size_t)l*DD*DD, pwimg + (size_t)(l*7+5)*16384);
        prep_w<<<128,128>>>(Wo + (size_t)l*DD*DD, pwimg + (size_t)(l*7+6)*16384);
    }

    embed_k<<<BN, DD>>>(features, W_embed);
    knn_k<<<dim3(NN/256, BB), 256>>>(pos);

    for (int l = 0; l < LL; l++) {
        const float*  P1L = P1 + (size_t)l*3*DD;
        const __half* img = pwimg + (size_t)l*7*16384;

        hgemm<0><<<BN/128, 256, HG_SMEM>>>(pxh, img + 0*16384, pq, nullptr, nullptr);
        hgemm<0><<<BN/128, 256, HG_SMEM>>>(pxh, img + 1*16384, pk, nullptr, nullptr);
        hgemm<0><<<BN/128, 256, HG_SMEM>>>(pxh, img + 2*16384, pv, nullptr, nullptr);
        pt_fused<<<MBIG/128, 256, FU_SMEM>>>(P1L, img + 3*16384, img + 4*16384, img + 5*16384);
        hgemm<2><<<BN/128, 256, HG_SMEM>>>(pagg, img + 6*16384, pxh, px, px);
    }

    poolmax_k<<<BB*32, DD>>>();
    cls_k<<<BB, DD>>>(Wc1, Wc2, out);
}

// round 6
// speedup vs baseline: 3.0778x; 1.2197x over previous
#include <cuda_runtime.h>
#include <cuda_fp16.h>
#include <cstdint>
#include <math.h>

// Problem constants
#define BB   8
#define NN   4096
#define KK   16
#define DD   128
#define LL   2
#define NCLS 40
#define BN   (BB*NN)          // 32768
#define MBIG (BN*KK)          // 524288

// ---------------- scratch (device globals; no allocation allowed) -----------
__device__ float  g_x[BN*DD];                 // fp32 residual stream
__device__ __half g_xh[BN*DD];                // fp16 mirror of x
__device__ __half g_q[BN*DD];
__device__ __half g_k[BN*DD];
__device__ __half g_v[BN*DD];
__device__ __half g_agg[BN*DD];
__device__ int    g_idx[MBIG];
__device__ float  g_rel[MBIG*3];
__device__ float  g_pmax[BB*32*DD];
__device__ __half g_wimg[14*DD*DD];           // fp16 weight images, [n][k] per slot

// ---------------- helpers ----------------------------------------------------
__device__ __forceinline__ uint32_t h2u(__half2 h) { return *(uint32_t*)&h; }
__device__ __forceinline__ uint32_t smem_u32(const void* p) {
    uint32_t a;
    asm("{ .reg .u64 t; cvta.to.shared.u64 t, %1; cvt.u32.u64 %0, t; }" : "=r"(a) : "l"(p));
    return a;
}
__device__ __forceinline__ void cpa16(uint32_t dst, const void* src) {
    asm volatile("cp.async.ca.shared.global [%0], [%1], 16;" :: "r"(dst), "l"(src));
}
__device__ __forceinline__ void cpa_commit() {
    asm volatile("cp.async.commit_group;" ::: "memory");
}
template<int N> __device__ __forceinline__ void cpa_wait() {
    asm volatile("cp.async.wait_group %0;" :: "n"(N) : "memory");
}
__device__ __forceinline__ void mma16(float* d, const uint32_t* a, const uint32_t* b) {
    asm volatile(
        "mma.sync.aligned.m16n8k16.row.col.f32.f16.f16.f32 "
        "{%0,%1,%2,%3}, {%4,%5,%6,%7}, {%8,%9}, {%0,%1,%2,%3};"
        : "+f"(d[0]), "+f"(d[1]), "+f"(d[2]), "+f"(d[3])
        : "r"(a[0]), "r"(a[1]), "r"(a[2]), "r"(a[3]), "r"(b[0]), "r"(b[1]));
}

// MMA over one 64-half K chunk. A: b32 array, row stride sA, k base kb (b32).
// B: stage-local b32 array, row stride 36 (n-major). Warp tile 64x32.
__device__ __forceinline__ void mma_chunk16(const uint32_t* __restrict__ Au, int sA, int kb,
                                            const uint32_t* __restrict__ Bu,
                                            int r0, int c0, int ar, int ak,
                                            float acc[4][4][4]) {
#pragma unroll
    for (int ks = 0; ks < 4; ks++) {
        int ka = kb + ks*8;
        uint32_t af[4][4], bf[4][2];
#pragma unroll
        for (int mf = 0; mf < 4; mf++) {
            int r = r0 + mf*16 + ar;
            af[mf][0] = Au[r*sA + ka + ak];
            af[mf][1] = Au[(r+8)*sA + ka + ak];
            af[mf][2] = Au[r*sA + ka + ak + 4];
            af[mf][3] = Au[(r+8)*sA + ka + ak + 4];
        }
#pragma unroll
        for (int nf = 0; nf < 4; nf++) {
            int cc = c0 + nf*8 + ar;
            bf[nf][0] = Bu[cc*36 + ks*8 + ak];
            bf[nf][1] = Bu[cc*36 + ks*8 + ak + 4];
        }
#pragma unroll
        for (int mf = 0; mf < 4; mf++)
#pragma unroll
            for (int nf = 0; nf < 4; nf++)
                mma16(acc[mf][nf], af[mf], bf[nf]);
    }
}

// B stage loader: Bimg [n=128][k=128] fp16, chunk k0 (halves), stage stride 36 b32
__device__ __forceinline__ void loadB(uint32_t bsm, const __half* __restrict__ Bimg,
                                      int k0, int t) {
#pragma unroll
    for (int i = 0; i < 4; i++) {
        int idx = t + i*256;
        int n = idx >> 3, seg = idx & 7;
        cpa16(bsm + (uint32_t)(n*144 + seg*16), Bimg + (size_t)n*128 + k0 + seg*8);
    }
}
// A stage loader from fp16 global [m][128]
__device__ __forceinline__ void loadA(uint32_t asmb, const __half* __restrict__ A,
                                      int mBase, int k0, int t) {
#pragma unroll
    for (int i = 0; i < 4; i++) {
        int idx = t + i*256;
        int row = idx >> 3, seg = idx & 7;
        cpa16(asmb + (uint32_t)(row*144 + seg*16), A + (size_t)(mBase+row)*128 + k0 + seg*8);
    }
}

// ---------------- weight image prep: 14 slots in one launch ------------------
__global__ void prep_all(const float* __restrict__ Wq, const float* __restrict__ Wk,
                         const float* __restrict__ Wv, const float* __restrict__ P2,
                         const float* __restrict__ G1, const float* __restrict__ G2,
                         const float* __restrict__ Wo, __half* __restrict__ dst) {
    int slot = blockIdx.y;
    int l = slot / 7, w = slot % 7;
    const float* src;
    switch (w) {
        case 0: src = Wq; break;  case 1: src = Wk; break;
        case 2: src = Wv; break;  case 3: src = P2; break;
        case 4: src = G1; break;  case 5: src = G2; break;
        default: src = Wo; break;
    }
    src += (size_t)l*DD*DD;
    int n = blockIdx.x, k = threadIdx.x;
    dst[(size_t)slot*16384 + n*128 + k] = __float2half(src[k*128 + n]);
}

// ======================= fused q/k/v GEMM: one A tile, 3 weights ============
#define QKV_SMEM (6*4608*4)   // Ast[2] + Bst[2] + pad room: 110592 B
__global__ __launch_bounds__(256, 2) void qkv3(const __half* __restrict__ A,
                                               const __half* __restrict__ B0,
                                               const __half* __restrict__ B1,
                                               const __half* __restrict__ B2,
                                               __half* __restrict__ O0,
                                               __half* __restrict__ O1,
                                               __half* __restrict__ O2) {
    extern __shared__ float sm[];
    uint32_t* Ast[2] = { (uint32_t*)sm, (uint32_t*)sm + 4608 };
    uint32_t* Bst[2] = { (uint32_t*)sm + 9216, (uint32_t*)sm + 13824 };
    int t = threadIdx.x;
    int mBase = blockIdx.x * 128;
    int lane = t & 31, wid = t >> 5;
    int r0 = (wid & 1) * 64, c0 = (wid >> 1) * 32;
    int ar = lane >> 2, ak = lane & 3;

    const __half* Bimg[3] = { B0, B1, B2 };
    __half* Out[3] = { O0, O1, O2 };

    loadA(smem_u32(Ast[0]), A, mBase, 0, t);
    loadA(smem_u32(Ast[1]), A, mBase, 64, t);
    loadB(smem_u32(Bst[0]), B0, 0, t);
    cpa_commit();
    loadB(smem_u32(Bst[1]), B0, 64, t);
    cpa_commit();

#pragma unroll
    for (int w = 0; w < 3; w++) {
        float acc[4][4][4] = {};
        // chunk 0
        cpa_wait<1>(); __syncthreads();
        mma_chunk16(Ast[0], 36, 0, Bst[0], r0, c0, ar, ak, acc);
        __syncthreads();
        if (w < 2) { loadB(smem_u32(Bst[0]), Bimg[w+1], 0, t); cpa_commit(); }
        // chunk 1
        if (w < 2) cpa_wait<1>(); else cpa_wait<0>();
        __syncthreads();
        mma_chunk16(Ast[1], 36, 0, Bst[1], r0, c0, ar, ak, acc);
        __syncthreads();
        if (w < 2) { loadB(smem_u32(Bst[1]), Bimg[w+1], 64, t); cpa_commit(); }
        // epilogue
        __half* C = Out[w];
#pragma unroll
        for (int mf = 0; mf < 4; mf++)
#pragma unroll
        for (int nf = 0; nf < 4; nf++) {
            int r = mBase + r0 + mf*16 + ar;
            int c = c0 + nf*8 + 2*ak;
            *(__half2*)(C + (size_t)r*128 + c) =
                __floats2half2_rn(acc[mf][nf][0], acc[mf][nf][1]);
            *(__half2*)(C + (size_t)(r+8)*128 + c) =
                __floats2half2_rn(acc[mf][nf][2], acc[mf][nf][3]);
        }
    }
}

// ======================= residual GEMM: Cf = Res + A@W, Ch = half(Cf) =======
#define HG_SMEM (4*4608*4)    // 73728 B
__global__ __launch_bounds__(256, 2) void hgemm_res(const __half* __restrict__ A,
                                                    const __half* __restrict__ Bimg,
                                                    __half* __restrict__ Ch,
                                                    float* __restrict__ Cf,
                                                    const float* __restrict__ Res) {
    extern __shared__ float sm[];
    uint32_t* Ast[2] = { (uint32_t*)sm, (uint32_t*)sm + 4608 };
    uint32_t* Bst[2] = { (uint32_t*)sm + 9216, (uint32_t*)sm + 13824 };
    int t = threadIdx.x;
    int mBase = blockIdx.x * 128;

    loadA(smem_u32(Ast[0]), A, mBase, 0, t);
    loadB(smem_u32(Bst[0]), Bimg, 0, t);
    cpa_commit();
    loadA(smem_u32(Ast[1]), A, mBase, 64, t);
    loadB(smem_u32(Bst[1]), Bimg, 64, t);
    cpa_commit();

    int lane = t & 31, wid = t >> 5;
    int r0 = (wid & 1) * 64, c0 = (wid >> 1) * 32;
    int ar = lane >> 2, ak = lane & 3;
    float acc[4][4][4] = {};

    cpa_wait<1>(); __syncthreads();
    mma_chunk16(Ast[0], 36, 0, Bst[0], r0, c0, ar, ak, acc);
    cpa_wait<0>(); __syncthreads();
    mma_chunk16(Ast[1], 36, 0, Bst[1], r0, c0, ar, ak, acc);

#pragma unroll
    for (int mf = 0; mf < 4; mf++)
#pragma unroll
    for (int nf = 0; nf < 4; nf++) {
        int r = mBase + r0 + mf*16 + ar;
        int c = c0 + nf*8 + 2*ak;
        float2 v0 = make_float2(acc[mf][nf][0], acc[mf][nf][1]);
        float2 v1 = make_float2(acc[mf][nf][2], acc[mf][nf][3]);
        float2 a0 = *(const float2*)(Res + (size_t)r*128 + c);
        float2 a1 = *(const float2*)(Res + (size_t)(r+8)*128 + c);
        v0.x += a0.x; v0.y += a0.y; v1.x += a1.x; v1.y += a1.y;
        *(float2*)(Cf + (size_t)r*128 + c) = v0;
        *(float2*)(Cf + (size_t)(r+8)*128 + c) = v1;
        *(__half2*)(Ch + (size_t)r*128 + c) = __floats2half2_rn(v0.x, v0.y);
        *(__half2*)(Ch + (size_t)(r+8)*128 + c) = __floats2half2_rn(v1.x, v1.y);
    }
}

// ======== fused per-neighbor block: delta -> g -> h2 -> logits -> agg =======
// smem layout (float offsets), total 27136 floats = 108544 B -> 2 CTAs/SM:
//   DlH  (half, stride 68 b32/row, 128 rows)  @ 0      .. 8704
//   Ast[2] (4608 b32 each)                    @ 8704   .. 17920   (Hu aliases)
//   Bst[2] (4608 b32 each)                    @ 17920  .. 27136
//   Ls (fp32, stride 132, 128 rows)           @ 8704   .. 25600   (after GEMM3)
#define FU_SMEM (27136*4)
__global__ __launch_bounds__(256, 2) void pt_fused(const float* __restrict__ P1L,
                                                   const __half* __restrict__ P2img,
                                                   const __half* __restrict__ G1img,
                                                   const __half* __restrict__ G2img) {
    extern __shared__ float sm[];
    uint32_t* DlH = (uint32_t*)sm;                         // half2 pairs, stride 68
    uint32_t* Ast[2] = { (uint32_t*)(sm + 8704), (uint32_t*)(sm + 13312) };
    uint32_t* Hu = (uint32_t*)(sm + 8704);                 // aliases Ast, stride 68
    uint32_t* Bst[2] = { (uint32_t*)(sm + 17920), (uint32_t*)(sm + 22528) };
    float*    Ls = sm + 8704;                              // stride 132

    __shared__ int   rowK[128];
    __shared__ float relS[128][3];
    __shared__ float P1s[3][128];

    int t = threadIdx.x;
    int mBase = blockIdx.x * 128;
    int lane = t & 31, wid = t >> 5;
    int r0 = (wid & 1) * 64, c0 = (wid >> 1) * 32;
    int ar = lane >> 2, ak = lane & 3;

    if (t < 128) {
        int m = mBase + t;
        rowK[t] = ((m >> 4) >> 12) * NN + g_idx[m];
        relS[t][0] = g_rel[(size_t)m*3+0];
        relS[t][1] = g_rel[(size_t)m*3+1];
        relS[t][2] = g_rel[(size_t)m*3+2];
    }
    for (int i = t; i < 384; i += 256) P1s[i/128][i%128] = P1L[i];
    __syncthreads();

    float acc[4][4][4] = {};

    // ================= GEMM1: delta = relu(rel@P1) @ P2 -> DlH ==============
    {
        loadB(smem_u32(Bst[0]), P2img, 0, t);  cpa_commit();
        loadB(smem_u32(Bst[1]), P2img, 64, t); cpa_commit();
#pragma unroll
        for (int st = 0; st < 2; st++) {
            int k0 = st*64;
#pragma unroll
            for (int i = 0; i < 16; i++) {
                int idx = t + i*256;
                int row = idx >> 5, j = idx & 31;
                int c = k0 + 2*j;
                float a0 = relS[row][0], a1 = relS[row][1], a2 = relS[row][2];
                float v0 = fmaxf(a0*P1s[0][c]   + a1*P1s[1][c]   + a2*P1s[2][c],   0.f);
                float v1 = fmaxf(a0*P1s[0][c+1] + a1*P1s[1][c+1] + a2*P1s[2][c+1], 0.f);
                Ast[st][row*36 + j] = h2u(__floats2half2_rn(v0, v1));
            }
        }
        cpa_wait<1>(); __syncthreads();
        mma_chunk16(Ast[0], 36, 0, Bst[0], r0, c0, ar, ak, acc);
        cpa_wait<0>(); __syncthreads();
        mma_chunk16(Ast[1], 36, 0, Bst[1], r0, c0, ar, ak, acc);
        __syncthreads();
#pragma unroll
        for (int mf = 0; mf < 4; mf++)
#pragma unroll
        for (int nf = 0; nf < 4; nf++) {
            int r = r0 + mf*16 + ar;
            int cb = (c0 + nf*8) >> 1;
            DlH[r*68 + cb + ak] = h2u(__floats2half2_rn(acc[mf][nf][0], acc[mf][nf][1]));
            DlH[(r+8)*68 + cb + ak] = h2u(__floats2half2_rn(acc[mf][nf][2], acc[mf][nf][3]));
            acc[mf][nf][0] = acc[mf][nf][1] = acc[mf][nf][2] = acc[mf][nf][3] = 0.f;
        }
        __syncthreads();
    }

    // ================= GEMM2: h2 = relu((q - k_g + delta) @ G1) -> Hu =======
    {
        loadB(smem_u32(Bst[0]), G1img, 0, t);  cpa_commit();
        loadB(smem_u32(Bst[1]), G1img, 64, t); cpa_commit();
        const __half* DlHh = (const __half*)DlH;
#pragma unroll
        for (int st = 0; st < 2; st++) {
            int k0 = st*64;
#pragma unroll
            for (int i = 0; i < 16; i++) {
                int idx = t + i*256;
                int row = idx >> 5, j = idx & 31;
                int c = k0 + 2*j;
                int bn = (mBase + row) >> 4;
                __half2 qh = *(const __half2*)(g_q + (size_t)bn*128 + c);
                __half2 kh = *(const __half2*)(g_k + (size_t)rowK[row]*128 + c);
                __half2 dh = *(const __half2*)(DlHh + row*136 + c);
                float v0 = __half2float(qh.x) - __half2float(kh.x) + __half2float(dh.x);
                float v1 = __half2float(qh.y) - __half2float(kh.y) + __half2float(dh.y);
                Ast[st][row*36 + j] = h2u(__floats2half2_rn(v0, v1));
            }
        }
        cpa_wait<1>(); __syncthreads();
        mma_chunk16(Ast[0], 36, 0, Bst[0], r0, c0, ar, ak, acc);
        cpa_wait<0>(); __syncthreads();
        mma_chunk16(Ast[1], 36, 0, Bst[1], r0, c0, ar, ak, acc);
        __syncthreads();                 // all warps done reading Ast
#pragma unroll
        for (int mf = 0; mf < 4; mf++)
#pragma unroll
        for (int nf = 0; nf < 4; nf++) {
            int r = r0 + mf*16 + ar;
            int cb = (c0 + nf*8) >> 1;
            Hu[r*68 + cb + ak] = h2u(__floats2half2_rn(
                fmaxf(acc[mf][nf][0], 0.f), fmaxf(acc[mf][nf][1], 0.f)));
            Hu[(r+8)*68 + cb + ak] = h2u(__floats2half2_rn(
                fmaxf(acc[mf][nf][2], 0.f), fmaxf(acc[mf][nf][3], 0.f)));
            acc[mf][nf][0] = acc[mf][nf][1] = acc[mf][nf][2] = acc[mf][nf][3] = 0.f;
        }
        __syncthreads();
    }

    // ================= GEMM3: logits = h2 @ G2 ==============================
    {
        loadB(smem_u32(Bst[0]), G2img, 0, t);  cpa_commit();
        loadB(smem_u32(Bst[1]), G2img, 64, t); cpa_commit();
        cpa_wait<1>(); __syncthreads();
        mma_chunk16(Hu, 68, 0,  Bst[0], r0, c0, ar, ak, acc);
        cpa_wait<0>(); __syncthreads();
        mma_chunk16(Hu, 68, 32, Bst[1], r0, c0, ar, ak, acc);
        __syncthreads();                 // Hu/Bst dead -> safe to write Ls
#pragma unroll
        for (int mf = 0; mf < 4; mf++)
#pragma unroll
        for (int nf = 0; nf < 4; nf++) {
            int r = r0 + mf*16 + ar;
            int c = c0 + nf*8 + 2*ak;
            Ls[r*132 + c]       = acc[mf][nf][0];
            Ls[r*132 + c+1]     = acc[mf][nf][1];
            Ls[(r+8)*132 + c]   = acc[mf][nf][2];
            Ls[(r+8)*132 + c+1] = acc[mf][nf][3];
        }
        __syncthreads();
    }

    // ================= softmax over K + aggregate ===========================
    const __half* DlHh = (const __half*)DlH;
    for (int it = t; it < 1024; it += 256) {
        int p = it >> 7, d = it & 127;
        float lo[KK];
        float mx = -3.4e38f;
#pragma unroll
        for (int k = 0; k < KK; k++) {
            lo[k] = Ls[(p*16 + k)*132 + d];
            mx = fmaxf(mx, lo[k]);
        }
        float s = 0.f;
#pragma unroll
        for (int k = 0; k < KK; k++) { lo[k] = expf(lo[k] - mx); s += lo[k]; }
        float inv = 1.f / s;
        float a = 0.f;
#pragma unroll
        for (int k = 0; k < KK; k++) {
            float vj = __half2float(g_v[(size_t)rowK[p*16+k]*128 + d]);
            float dl = __half2float(DlHh[(p*16 + k)*136 + d]);
            a += lo[k]*inv*(vj + dl);
        }
        g_agg[(size_t)((mBase >> 4) + p)*128 + d] = __float2half(a);
    }
}

// ---------------- embedding: x = relu(features @ W_embed) -------------------
__global__ void embed_k(const float* __restrict__ f, const float* __restrict__ W) {
    int m = blockIdx.x;
    int d = threadIdx.x;
    float f0 = f[m*3+0], f1 = f[m*3+1], f2 = f[m*3+2];
    float v = fmaxf(f0*W[d] + f1*W[DD+d] + f2*W[2*DD+d], 0.f);
    g_x[m*DD + d] = v;
    g_xh[m*DD + d] = __float2half(v);
}

// ---------------- kNN (top-16 smallest d2, incl self) + rel -----------------
#define TJ 1024
__global__ __launch_bounds__(256) void knn_k(const float* __restrict__ pos) {
    int b = blockIdx.y;
    int i = blockIdx.x*256 + threadIdx.x;
    const float* pb = pos + (size_t)b*NN*3;
    float px = pb[i*3+0], py = pb[i*3+1], pz = pb[i*3+2];
    float sqi = px*px + py*py + pz*pz;

    float bd[KK]; int bi[KK];
#pragma unroll
    for (int t = 0; t < KK; t++) { bd[t] = 3.4e38f; bi[t] = -1; }
    float worst = 3.4e38f; int wslot = 0;

    __shared__ float sp[TJ*3];
    __shared__ float ssq[TJ];

    for (int j0 = 0; j0 < NN; j0 += TJ) {
        for (int t = threadIdx.x; t < TJ; t += 256) {
            float a = pb[(j0+t)*3+0];
            float c1 = pb[(j0+t)*3+1];
            float c2 = pb[(j0+t)*3+2];
            sp[t*3+0] = a; sp[t*3+1] = c1; sp[t*3+2] = c2;
            ssq[t] = a*a + c1*c1 + c2*c2;
        }
        __syncthreads();
        for (int jj = 0; jj < TJ; jj++) {
            float dot = px*sp[jj*3] + py*sp[jj*3+1] + pz*sp[jj*3+2];
            float d2 = sqi + ssq[jj] - 2.0f*dot;
            if (d2 < worst) {
                bd[wslot] = d2; bi[wslot] = j0 + jj;
                worst = bd[0]; wslot = 0;
#pragma unroll
                for (int t = 1; t < KK; t++)
                    if (bd[t] > worst) { worst = bd[t]; wslot = t; }
            }
        }
        __syncthreads();
    }
    int base = (b*NN + i)*KK;
#pragma unroll
    for (int t = 0; t < KK; t++) {
        int j = bi[t];
        g_idx[base + t] = j;
        g_rel[(size_t)(base+t)*3+0] = px - pb[j*3+0];
        g_rel[(size_t)(base+t)*3+1] = py - pb[j*3+1];
        g_rel[(size_t)(base+t)*3+2] = pz - pb[j*3+2];
    }
}

// ---------------- global max pool (partial) ---------------------------------
__global__ void poolmax_k() {
    int b  = blockIdx.x >> 5;
    int ch = blockIdx.x & 31;
    int d  = threadIdx.x;
    float m = -3.4e38f;
    for (int n = ch*128; n < ch*128 + 128; n++)
        m = fmaxf(m, g_x[((size_t)b*NN + n)*DD + d]);
    g_pmax[(size_t)blockIdx.x*DD + d] = m;
}

// ---------------- classifier head -------------------------------------------
__global__ void cls_k(const float* __restrict__ Wc1, const float* __restrict__ Wc2,
                      float* __restrict__ out) {
    int b = blockIdx.x;
    int d = threadIdx.x;
    __shared__ float pooled[DD];
    __shared__ float h[DD];
    float m = -3.4e38f;
    for (int ch = 0; ch < 32; ch++)
        m = fmaxf(m, g_pmax[((size_t)b*32 + ch)*DD + d]);
    pooled[d] = m;
    __syncthreads();
    float acc = 0.f;
    for (int c = 0; c < DD; c++) acc += pooled[c]*Wc1[c*DD + d];
    h[d] = fmaxf(acc, 0.f);
    __syncthreads();
    if (d < NCLS) {
        float o = 0.f;
        for (int c = 0; c < DD; c++) o += h[c]*Wc2[c*NCLS + d];
        out[b*NCLS + d] = o;
    }
}

// ---------------- launch -----------------------------------------------------
extern "C" void kernel_launch(void* const* d_in, const int* in_sizes, int n_in,
                              void* d_out, int out_size) {
    const float* features = (const float*)d_in[0];
    const float* pos      = (const float*)d_in[1];
    const float* W_embed  = (const float*)d_in[2];
    const float* Wq       = (const float*)d_in[3];
    const float* Wk       = (const float*)d_in[4];
    const float* Wv       = (const float*)d_in[5];
    const float* P1       = (const float*)d_in[6];
    const float* P2       = (const float*)d_in[7];
    const float* G1       = (const float*)d_in[8];
    const float* G2       = (const float*)d_in[9];
    const float* Wo       = (const float*)d_in[10];
    const float* Wc1      = (const float*)d_in[11];
    const float* Wc2      = (const float*)d_in[12];
    float* out = (float*)d_out;

    static float  *px = nullptr;
    static __half *pxh=nullptr, *pq=nullptr, *pk=nullptr, *pv=nullptr,
                  *pagg=nullptr, *pwimg=nullptr;
    if (!px) {
        cudaGetSymbolAddress((void**)&px,   g_x);
        cudaGetSymbolAddress((void**)&pxh,  g_xh);
        cudaGetSymbolAddress((void**)&pq,   g_q);
        cudaGetSymbolAddress((void**)&pk,   g_k);
        cudaGetSymbolAddress((void**)&pv,   g_v);
        cudaGetSymbolAddress((void**)&pagg, g_agg);
        cudaGetSymbolAddress((void**)&pwimg,g_wimg);
        cudaFuncSetAttribute(qkv3,      cudaFuncAttributeMaxDynamicSharedMemorySize, QKV_SMEM);
        cudaFuncSetAttribute(hgemm_res, cudaFuncAttributeMaxDynamicSharedMemorySize, HG_SMEM);
        cudaFuncSetAttribute(pt_fused,  cudaFuncAttributeMaxDynamicSharedMemorySize, FU_SMEM);
    }

    prep_all<<<dim3(128,14), 128>>>(Wq, Wk, Wv, P2, G1, G2, Wo, pwimg);
    embed_k<<<BN, DD>>>(features, W_embed);
    knn_k<<<dim3(NN/256, BB), 256>>>(pos);

    for (int l = 0; l < LL; l++) {
        const float*  P1L = P1 + (size_t)l*3*DD;
        const __half* img = pwimg + (size_t)l*7*16384;

        qkv3<<<BN/128, 256, QKV_SMEM>>>(pxh, img + 0*16384, img + 1*16384, img + 2*16384,
                                        pq, pk, pv);
        pt_fused<<<MBIG/128, 256, FU_SMEM>>>(P1L, img + 3*16384, img + 4*16384, img + 5*16384);
        hgemm_res<<<BN/128, 256, HG_SMEM>>>(pagg, img + 6*16384, pxh, px, px);
    }

    poolmax_k<<<BB*32, DD>>>();
    cls_k<<<BB, DD>>>(Wc1, Wc2, out);
}

// round 7
// speedup vs baseline: 3.2814x; 1.0661x over previous
#include <cuda_runtime.h>
#include <cuda_fp16.h>
#include <cstdint>
#include <math.h>

// Problem constants
#define BB   8
#define NN   4096
#define KK   16
#define DD   128
#define LL   2
#define NCLS 40
#define BN   (BB*NN)          // 32768
#define MBIG (BN*KK)          // 524288

// ---------------- scratch (device globals; no allocation allowed) -----------
__device__ float  g_x[BN*DD];                 // fp32 residual stream
__device__ __half g_xh[BN*DD];                // fp16 mirror of x
__device__ __half g_q[BN*DD];
__device__ __half g_k[BN*DD];
__device__ __half g_v[BN*DD];
__device__ __half g_agg[BN*DD];
__device__ int    g_idx[MBIG];
__device__ float  g_rel[MBIG*3];
__device__ float  g_pmax[BB*32*DD];
__device__ __half g_wimg[14*DD*DD];           // fp16 weight images, [n][k] per slot

// ---------------- helpers ----------------------------------------------------
__device__ __forceinline__ uint32_t h2u(__half2 h) { return *(uint32_t*)&h; }
__device__ __forceinline__ uint32_t smem_u32(const void* p) {
    uint32_t a;
    asm("{ .reg .u64 t; cvta.to.shared.u64 t, %1; cvt.u32.u64 %0, t; }" : "=r"(a) : "l"(p));
    return a;
}
__device__ __forceinline__ void cpa16(uint32_t dst, const void* src) {
    asm volatile("cp.async.ca.shared.global [%0], [%1], 16;" :: "r"(dst), "l"(src));
}
__device__ __forceinline__ void cpa_commit() {
    asm volatile("cp.async.commit_group;" ::: "memory");
}
template<int N> __device__ __forceinline__ void cpa_wait() {
    asm volatile("cp.async.wait_group %0;" :: "n"(N) : "memory");
}
__device__ __forceinline__ void mma16(float* d, const uint32_t* a, const uint32_t* b) {
    asm volatile(
        "mma.sync.aligned.m16n8k16.row.col.f32.f16.f16.f32 "
        "{%0,%1,%2,%3}, {%4,%5,%6,%7}, {%8,%9}, {%0,%1,%2,%3};"
        : "+f"(d[0]), "+f"(d[1]), "+f"(d[2]), "+f"(d[3])
        : "r"(a[0]), "r"(a[1]), "r"(a[2]), "r"(a[3]), "r"(b[0]), "r"(b[1]));
}
__device__ __forceinline__ void ldmx4(uint32_t* r, uint32_t addr) {
    asm volatile("ldmatrix.sync.aligned.m8n8.x4.shared.b16 {%0,%1,%2,%3}, [%4];"
                 : "=r"(r[0]), "=r"(r[1]), "=r"(r[2]), "=r"(r[3]) : "r"(addr));
}

// MMA over one 64-half K chunk using ldmatrix.
// Abase: smem addr (bytes) of A tile (b32 stride sA); kb = b32 k-offset.
// Bbase: smem addr of B stage, stride 36 b32, n-major. Warp tile 64x32 @ (r0,c0).
__device__ __forceinline__ void mma_chunk16(uint32_t Abase, int sA, int kb,
                                            uint32_t Bbase,
                                            int r0, int c0, int lane,
                                            float acc[4][4][4]) {
    int l7 = lane & 7;
    uint32_t rowA = (uint32_t)(r0 + l7 + ((lane >> 3) & 1) * 8);
    uint32_t colA = (uint32_t)((lane >> 4) * 4);
    uint32_t aAddr = Abase + (rowA * (uint32_t)sA + (uint32_t)kb + colA) * 4u;
    uint32_t rowB = (uint32_t)(c0 + l7 + (lane >> 4) * 8);
    uint32_t colB = (uint32_t)(((lane >> 3) & 1) * 4);
    uint32_t bAddr0 = Bbase + (rowB * 36u + colB) * 4u;
    uint32_t bAddr1 = bAddr0 + 16u * 36u * 4u;
    uint32_t aStepM = (uint32_t)(16 * sA * 4);

#pragma unroll
    for (int ks = 0; ks < 4; ks++) {
        uint32_t af[4][4], bf[2][4];
#pragma unroll
        for (int mf = 0; mf < 4; mf++)
            ldmx4(af[mf], aAddr + (uint32_t)mf * aStepM + (uint32_t)(ks * 32));
        ldmx4(bf[0], bAddr0 + (uint32_t)(ks * 32));
        ldmx4(bf[1], bAddr1 + (uint32_t)(ks * 32));
#pragma unroll
        for (int mf = 0; mf < 4; mf++) {
            mma16(acc[mf][0], af[mf], &bf[0][0]);
            mma16(acc[mf][1], af[mf], &bf[0][2]);
            mma16(acc[mf][2], af[mf], &bf[1][0]);
            mma16(acc[mf][3], af[mf], &bf[1][2]);
        }
    }
}

// B stage loader: Bimg [n=128][k=128] fp16, chunk k0 (halves), stage stride 36 b32
__device__ __forceinline__ void loadB(uint32_t bsm, const __half* __restrict__ Bimg,
                                      int k0, int t) {
#pragma unroll
    for (int i = 0; i < 4; i++) {
        int idx = t + i*256;
        int n = idx >> 3, seg = idx & 7;
        cpa16(bsm + (uint32_t)(n*144 + seg*16), Bimg + (size_t)n*128 + k0 + seg*8);
    }
}
// A stage loader from fp16 global [m][128]
__device__ __forceinline__ void loadA(uint32_t asmb, const __half* __restrict__ A,
                                      int mBase, int k0, int t) {
#pragma unroll
    for (int i = 0; i < 4; i++) {
        int idx = t + i*256;
        int row = idx >> 3, seg = idx & 7;
        cpa16(asmb + (uint32_t)(row*144 + seg*16), A + (size_t)(mBase+row)*128 + k0 + seg*8);
    }
}

// ---------------- weight image prep: 14 slots in one launch ------------------
__global__ void prep_all(const float* __restrict__ Wq, const float* __restrict__ Wk,
                         const float* __restrict__ Wv, const float* __restrict__ P2,
                         const float* __restrict__ G1, const float* __restrict__ G2,
                         const float* __restrict__ Wo, __half* __restrict__ dst) {
    int slot = blockIdx.y;
    int l = slot / 7, w = slot % 7;
    const float* src;
    switch (w) {
        case 0: src = Wq; break;  case 1: src = Wk; break;
        case 2: src = Wv; break;  case 3: src = P2; break;
        case 4: src = G1; break;  case 5: src = G2; break;
        default: src = Wo; break;
    }
    src += (size_t)l*DD*DD;
    int n = blockIdx.x, k = threadIdx.x;
    dst[(size_t)slot*16384 + n*128 + k] = __float2half(src[k*128 + n]);
}

// ======================= fused q/k/v GEMM: one A tile, 3 weights ============
#define QKV_SMEM (6*4608*4)
__global__ __launch_bounds__(256, 2) void qkv3(const __half* __restrict__ A,
                                               const __half* __restrict__ B0,
                                               const __half* __restrict__ B1,
                                               const __half* __restrict__ B2,
                                               __half* __restrict__ O0,
                                               __half* __restrict__ O1,
                                               __half* __restrict__ O2) {
    extern __shared__ float sm[];
    uint32_t* Ast[2] = { (uint32_t*)sm, (uint32_t*)sm + 4608 };
    uint32_t* Bst[2] = { (uint32_t*)sm + 9216, (uint32_t*)sm + 13824 };
    int t = threadIdx.x;
    int mBase = blockIdx.x * 128;
    int lane = t & 31, wid = t >> 5;
    int r0 = (wid & 1) * 64, c0 = (wid >> 1) * 32;
    int ar = lane >> 2, ak = lane & 3;

    const __half* Bimg[3] = { B0, B1, B2 };
    __half* Out[3] = { O0, O1, O2 };
    uint32_t uA0 = smem_u32(Ast[0]), uA1 = smem_u32(Ast[1]);
    uint32_t uB0 = smem_u32(Bst[0]), uB1 = smem_u32(Bst[1]);

    loadA(uA0, A, mBase, 0, t);
    loadA(uA1, A, mBase, 64, t);
    loadB(uB0, B0, 0, t);
    cpa_commit();
    loadB(uB1, B0, 64, t);
    cpa_commit();

#pragma unroll
    for (int w = 0; w < 3; w++) {
        float acc[4][4][4] = {};
        cpa_wait<1>(); __syncthreads();
        mma_chunk16(uA0, 36, 0, uB0, r0, c0, lane, acc);
        __syncthreads();
        if (w < 2) { loadB(uB0, Bimg[w+1], 0, t); cpa_commit(); }
        if (w < 2) cpa_wait<1>(); else cpa_wait<0>();
        __syncthreads();
        mma_chunk16(uA1, 36, 0, uB1, r0, c0, lane, acc);
        __syncthreads();
        if (w < 2) { loadB(uB1, Bimg[w+1], 64, t); cpa_commit(); }
        __half* C = Out[w];
#pragma unroll
        for (int mf = 0; mf < 4; mf++)
#pragma unroll
        for (int nf = 0; nf < 4; nf++) {
            int r = mBase + r0 + mf*16 + ar;
            int c = c0 + nf*8 + 2*ak;
            *(__half2*)(C + (size_t)r*128 + c) =
                __floats2half2_rn(acc[mf][nf][0], acc[mf][nf][1]);
            *(__half2*)(C + (size_t)(r+8)*128 + c) =
                __floats2half2_rn(acc[mf][nf][2], acc[mf][nf][3]);
        }
    }
}

// ======================= residual GEMM: Cf = Res + A@W, Ch = half(Cf) =======
#define HG_SMEM (4*4608*4)
__global__ __launch_bounds__(256, 2) void hgemm_res(const __half* __restrict__ A,
                                                    const __half* __restrict__ Bimg,
                                                    __half* __restrict__ Ch,
                                                    float* __restrict__ Cf,
                                                    const float* __restrict__ Res) {
    extern __shared__ float sm[];
    uint32_t* Ast[2] = { (uint32_t*)sm, (uint32_t*)sm + 4608 };
    uint32_t* Bst[2] = { (uint32_t*)sm + 9216, (uint32_t*)sm + 13824 };
    int t = threadIdx.x;
    int mBase = blockIdx.x * 128;
    uint32_t uA0 = smem_u32(Ast[0]), uA1 = smem_u32(Ast[1]);
    uint32_t uB0 = smem_u32(Bst[0]), uB1 = smem_u32(Bst[1]);

    loadA(uA0, A, mBase, 0, t);
    loadB(uB0, Bimg, 0, t);
    cpa_commit();
    loadA(uA1, A, mBase, 64, t);
    loadB(uB1, Bimg, 64, t);
    cpa_commit();

    int lane = t & 31, wid = t >> 5;
    int r0 = (wid & 1) * 64, c0 = (wid >> 1) * 32;
    int ar = lane >> 2, ak = lane & 3;
    float acc[4][4][4] = {};

    cpa_wait<1>(); __syncthreads();
    mma_chunk16(uA0, 36, 0, uB0, r0, c0, lane, acc);
    cpa_wait<0>(); __syncthreads();
    mma_chunk16(uA1, 36, 0, uB1, r0, c0, lane, acc);

#pragma unroll
    for (int mf = 0; mf < 4; mf++)
#pragma unroll
    for (int nf = 0; nf < 4; nf++) {
        int r = mBase + r0 + mf*16 + ar;
        int c = c0 + nf*8 + 2*ak;
        float2 v0 = make_float2(acc[mf][nf][0], acc[mf][nf][1]);
        float2 v1 = make_float2(acc[mf][nf][2], acc[mf][nf][3]);
        float2 a0 = *(const float2*)(Res + (size_t)r*128 + c);
        float2 a1 = *(const float2*)(Res + (size_t)(r+8)*128 + c);
        v0.x += a0.x; v0.y += a0.y; v1.x += a1.x; v1.y += a1.y;
        *(float2*)(Cf + (size_t)r*128 + c) = v0;
        *(float2*)(Cf + (size_t)(r+8)*128 + c) = v1;
        *(__half2*)(Ch + (size_t)r*128 + c) = __floats2half2_rn(v0.x, v0.y);
        *(__half2*)(Ch + (size_t)(r+8)*128 + c) = __floats2half2_rn(v1.x, v1.y);
    }
}

// ======== fused per-neighbor block: delta -> g -> h2 -> logits -> agg =======
// smem layout (float offsets), total 27136 floats = 108544 B -> 2 CTAs/SM:
//   DlH (half2, stride 68 b32/row)  @ 0      Ast[2] @ 8704 (Hu aliases)
//   Bst[2] @ 17920                  Ls (fp32, stride 132) @ 8704 after GEMM3
#define FU_SMEM (27136*4)
__global__ __launch_bounds__(256, 2) void pt_fused(const float* __restrict__ P1L,
                                                   const __half* __restrict__ P2img,
                                                   const __half* __restrict__ G1img,
                                                   const __half* __restrict__ G2img) {
    extern __shared__ float sm[];
    uint32_t* DlH = (uint32_t*)sm;
    uint32_t* Ast[2] = { (uint32_t*)(sm + 8704), (uint32_t*)(sm + 13312) };
    uint32_t* Bst[2] = { (uint32_t*)(sm + 17920), (uint32_t*)(sm + 22528) };
    float*    Ls = sm + 8704;

    __shared__ int   rowK[128];
    __shared__ float relS[128][3];
    __shared__ float P1s[3][128];

    int t = threadIdx.x;
    int mBase = blockIdx.x * 128;
    int lane = t & 31, wid = t >> 5;
    int r0 = (wid & 1) * 64, c0 = (wid >> 1) * 32;
    int ar = lane >> 2, ak = lane & 3;
    uint32_t uA0 = smem_u32(Ast[0]), uA1 = smem_u32(Ast[1]);
    uint32_t uB0 = smem_u32(Bst[0]), uB1 = smem_u32(Bst[1]);
    uint32_t uHu = uA0;

    if (t < 128) {
        int m = mBase + t;
        rowK[t] = ((m >> 4) >> 12) * NN + g_idx[m];
        relS[t][0] = g_rel[(size_t)m*3+0];
        relS[t][1] = g_rel[(size_t)m*3+1];
        relS[t][2] = g_rel[(size_t)m*3+2];
    }
    for (int i = t; i < 384; i += 256) P1s[i/128][i%128] = P1L[i];
    __syncthreads();

    float acc[4][4][4] = {};

    // ================= GEMM1: delta = relu(rel@P1) @ P2 -> DlH ==============
    {
        loadB(uB0, P2img, 0, t);  cpa_commit();
        loadB(uB1, P2img, 64, t); cpa_commit();
#pragma unroll
        for (int st = 0; st < 2; st++) {
            int k0 = st*64;
#pragma unroll
            for (int i = 0; i < 16; i++) {
                int idx = t + i*256;
                int row = idx >> 5, j = idx & 31;
                int c = k0 + 2*j;
                float a0 = relS[row][0], a1 = relS[row][1], a2 = relS[row][2];
                float v0 = fmaxf(a0*P1s[0][c]   + a1*P1s[1][c]   + a2*P1s[2][c],   0.f);
                float v1 = fmaxf(a0*P1s[0][c+1] + a1*P1s[1][c+1] + a2*P1s[2][c+1], 0.f);
                Ast[st][row*36 + j] = h2u(__floats2half2_rn(v0, v1));
            }
        }
        cpa_wait<1>(); __syncthreads();
        mma_chunk16(uA0, 36, 0, uB0, r0, c0, lane, acc);
        cpa_wait<0>(); __syncthreads();
        mma_chunk16(uA1, 36, 0, uB1, r0, c0, lane, acc);
        __syncthreads();
#pragma unroll
        for (int mf = 0; mf < 4; mf++)
#pragma unroll
        for (int nf = 0; nf < 4; nf++) {
            int r = r0 + mf*16 + ar;
            int cb = (c0 + nf*8) >> 1;
            DlH[r*68 + cb + ak] = h2u(__floats2half2_rn(acc[mf][nf][0], acc[mf][nf][1]));
            DlH[(r+8)*68 + cb + ak] = h2u(__floats2half2_rn(acc[mf][nf][2], acc[mf][nf][3]));
            acc[mf][nf][0] = acc[mf][nf][1] = acc[mf][nf][2] = acc[mf][nf][3] = 0.f;
        }
        __syncthreads();
    }

    // ================= GEMM2: h2 = relu((q - k_g + delta) @ G1) -> Hu =======
    {
        loadB(uB0, G1img, 0, t);  cpa_commit();
        loadB(uB1, G1img, 64, t); cpa_commit();
        const __half* DlHh = (const __half*)DlH;
#pragma unroll
        for (int st = 0; st < 2; st++) {
            int k0 = st*64;
#pragma unroll
            for (int i = 0; i < 16; i++) {
                int idx = t + i*256;
                int row = idx >> 5, j = idx & 31;
                int c = k0 + 2*j;
                int bn = (mBase + row) >> 4;
                __half2 qh = *(const __half2*)(g_q + (size_t)bn*128 + c);
                __half2 kh = *(const __half2*)(g_k + (size_t)rowK[row]*128 + c);
                __half2 dh = *(const __half2*)(DlHh + row*136 + c);
                float v0 = __half2float(qh.x) - __half2float(kh.x) + __half2float(dh.x);
                float v1 = __half2float(qh.y) - __half2float(kh.y) + __half2float(dh.y);
                Ast[st][row*36 + j] = h2u(__floats2half2_rn(v0, v1));
            }
        }
        cpa_wait<1>(); __syncthreads();
        mma_chunk16(uA0, 36, 0, uB0, r0, c0, lane, acc);
        cpa_wait<0>(); __syncthreads();
        mma_chunk16(uA1, 36, 0, uB1, r0, c0, lane, acc);
        __syncthreads();
        uint32_t* Hu = (uint32_t*)Ast[0];
#pragma unroll
        for (int mf = 0; mf < 4; mf++)
#pragma unroll
        for (int nf = 0; nf < 4; nf++) {
            int r = r0 + mf*16 + ar;
            int cb = (c0 + nf*8) >> 1;
            Hu[r*68 + cb + ak] = h2u(__floats2half2_rn(
                fmaxf(acc[mf][nf][0], 0.f), fmaxf(acc[mf][nf][1], 0.f)));
            Hu[(r+8)*68 + cb + ak] = h2u(__floats2half2_rn(
                fmaxf(acc[mf][nf][2], 0.f), fmaxf(acc[mf][nf][3], 0.f)));
            acc[mf][nf][0] = acc[mf][nf][1] = acc[mf][nf][2] = acc[mf][nf][3] = 0.f;
        }
        __syncthreads();
    }

    // ================= GEMM3: logits = h2 @ G2 ==============================
    {
        loadB(uB0, G2img, 0, t);  cpa_commit();
        loadB(uB1, G2img, 64, t); cpa_commit();
        cpa_wait<1>(); __syncthreads();
        mma_chunk16(uHu, 68, 0,  uB0, r0, c0, lane, acc);
        cpa_wait<0>(); __syncthreads();
        mma_chunk16(uHu, 68, 32, uB1, r0, c0, lane, acc);
        __syncthreads();
#pragma unroll
        for (int mf = 0; mf < 4; mf++)
#pragma unroll
        for (int nf = 0; nf < 4; nf++) {
            int r = r0 + mf*16 + ar;
            int c = c0 + nf*8 + 2*ak;
            Ls[r*132 + c]       = acc[mf][nf][0];
            Ls[r*132 + c+1]     = acc[mf][nf][1];
            Ls[(r+8)*132 + c]   = acc[mf][nf][2];
            Ls[(r+8)*132 + c+1] = acc[mf][nf][3];
        }
        __syncthreads();
    }

    // ================= softmax over K + aggregate ===========================
    const __half* DlHh = (const __half*)DlH;
    for (int it = t; it < 1024; it += 256) {
        int p = it >> 7, d = it & 127;
        float lo[KK];
        float mx = -3.4e38f;
#pragma unroll
        for (int k = 0; k < KK; k++) {
            lo[k] = Ls[(p*16 + k)*132 + d];
            mx = fmaxf(mx, lo[k]);
        }
        float s = 0.f;
#pragma unroll
        for (int k = 0; k < KK; k++) { lo[k] = expf(lo[k] - mx); s += lo[k]; }
        float inv = 1.f / s;
        float a = 0.f;
#pragma unroll
        for (int k = 0; k < KK; k++) {
            float vj = __half2float(g_v[(size_t)rowK[p*16+k]*128 + d]);
            float dl = __half2float(DlHh[(p*16 + k)*136 + d]);
            a += lo[k]*inv*(vj + dl);
        }
        g_agg[(size_t)((mBase >> 4) + p)*128 + d] = __float2half(a);
    }
}

// ---------------- embedding: x = relu(features @ W_embed) -------------------
__global__ void embed_k(const float* __restrict__ f, const float* __restrict__ W) {
    int m = blockIdx.x;
    int d = threadIdx.x;
    float f0 = f[m*3+0], f1 = f[m*3+1], f2 = f[m*3+2];
    float v = fmaxf(f0*W[d] + f1*W[DD+d] + f2*W[2*DD+d], 0.f);
    g_x[m*DD + d] = v;
    g_xh[m*DD + d] = __float2half(v);
}

// ---------------- kNN (top-16 smallest d2, incl self) + rel -----------------
#define TJ 1024
__global__ __launch_bounds__(256) void knn_k(const float* __restrict__ pos) {
    int b = blockIdx.y;
    int i = blockIdx.x*256 + threadIdx.x;
    const float* pb = pos + (size_t)b*NN*3;
    float px = pb[i*3+0], py = pb[i*3+1], pz = pb[i*3+2];
    float sqi = px*px + py*py + pz*pz;

    float bd[KK]; int bi[KK];
#pragma unroll
    for (int t = 0; t < KK; t++) { bd[t] = 3.4e38f; bi[t] = -1; }
    float worst = 3.4e38f; int wslot = 0;

    __shared__ float sp[TJ*3];
    __shared__ float ssq[TJ];

    for (int j0 = 0; j0 < NN; j0 += TJ) {
        for (int t = threadIdx.x; t < TJ; t += 256) {
            float a = pb[(j0+t)*3+0];
            float c1 = pb[(j0+t)*3+1];
            float c2 = pb[(j0+t)*3+2];
            sp[t*3+0] = a; sp[t*3+1] = c1; sp[t*3+2] = c2;
            ssq[t] = a*a + c1*c1 + c2*c2;
        }
        __syncthreads();
        for (int jj = 0; jj < TJ; jj++) {
            float dot = px*sp[jj*3] + py*sp[jj*3+1] + pz*sp[jj*3+2];
            float d2 = sqi + ssq[jj] - 2.0f*dot;
            if (d2 < worst) {
                bd[wslot] = d2; bi[wslot] = j0 + jj;
                worst = bd[0]; wslot = 0;
#pragma unroll
                for (int t = 1; t < KK; t++)
                    if (bd[t] > worst) { worst = bd[t]; wslot = t; }
            }
        }
        __syncthreads();
    }
    int base = (b*NN + i)*KK;
#pragma unroll
    for (int t = 0; t < KK; t++) {
        int j = bi[t];
        g_idx[base + t] = j;
        g_rel[(size_t)(base+t)*3+0] = px - pb[j*3+0];
        g_rel[(size_t)(base+t)*3+1] = py - pb[j*3+1];
        g_rel[(size_t)(base+t)*3+2] = pz - pb[j*3+2];
    }
}

// ---------------- global max pool (partial) ---------------------------------
__global__ void poolmax_k() {
    int b  = blockIdx.x >> 5;
    int ch = blockIdx.x & 31;
    int d  = threadIdx.x;
    float m = -3.4e38f;
    for (int n = ch*128; n < ch*128 + 128; n++)
        m = fmaxf(m, g_x[((size_t)b*NN + n)*DD + d]);
    g_pmax[(size_t)blockIdx.x*DD + d] = m;
}

// ---------------- classifier head -------------------------------------------
__global__ void cls_k(const float* __restrict__ Wc1, const float* __restrict__ Wc2,
                      float* __restrict__ out) {
    int b = blockIdx.x;
    int d = threadIdx.x;
    __shared__ float pooled[DD];
    __shared__ float h[DD];
    float m = -3.4e38f;
    for (int ch = 0; ch < 32; ch++)
        m = fmaxf(m, g_pmax[((size_t)b*32 + ch)*DD + d]);
    pooled[d] = m;
    __syncthreads();
    float acc = 0.f;
    for (int c = 0; c < DD; c++) acc += pooled[c]*Wc1[c*DD + d];
    h[d] = fmaxf(acc, 0.f);
    __syncthreads();
    if (d < NCLS) {
        float o = 0.f;
        for (int c = 0; c < DD; c++) o += h[c]*Wc2[c*NCLS + d];
        out[b*NCLS + d] = o;
    }
}

// ---------------- launch -----------------------------------------------------
extern "C" void kernel_launch(void* const* d_in, const int* in_sizes, int n_in,
                              void* d_out, int out_size) {
    const float* features = (const float*)d_in[0];
    const float* pos      = (const float*)d_in[1];
    const float* W_embed  = (const float*)d_in[2];
    const float* Wq       = (const float*)d_in[3];
    const float* Wk       = (const float*)d_in[4];
    const float* Wv       = (const float*)d_in[5];
    const float* P1       = (const float*)d_in[6];
    const float* P2       = (const float*)d_in[7];
    const float* G1       = (const float*)d_in[8];
    const float* G2       = (const float*)d_in[9];
    const float* Wo       = (const float*)d_in[10];
    const float* Wc1      = (const float*)d_in[11];
    const float* Wc2      = (const float*)d_in[12];
    float* out = (float*)d_out;

    static float  *px = nullptr;
    static __half *pxh=nullptr, *pq=nullptr, *pk=nullptr, *pv=nullptr,
                  *pagg=nullptr, *pwimg=nullptr;
    if (!px) {
        cudaGetSymbolAddress((void**)&px,   g_x);
        cudaGetSymbolAddress((void**)&pxh,  g_xh);
        cudaGetSymbolAddress((void**)&pq,   g_q);
        cudaGetSymbolAddress((void**)&pk,   g_k);
        cudaGetSymbolAddress((void**)&pv,   g_v);
        cudaGetSymbolAddress((void**)&pagg, g_agg);
        cudaGetSymbolAddress((void**)&pwimg,g_wimg);
        cudaFuncSetAttribute(qkv3,      cudaFuncAttributeMaxDynamicSharedMemorySize, QKV_SMEM);
        cudaFuncSetAttribute(hgemm_res, cudaFuncAttributeMaxDynamicSharedMemorySize, HG_SMEM);
        cudaFuncSetAttribute(pt_fused,  cudaFuncAttributeMaxDynamicSharedMemorySize, FU_SMEM);
    }

    prep_all<<<dim3(128,14), 128>>>(Wq, Wk, Wv, P2, G1, G2, Wo, pwimg);
    embed_k<<<BN, DD>>>(features, W_embed);
    knn_k<<<dim3(NN/256, BB), 256>>>(pos);

    for (int l = 0; l < LL; l++) {
        const float*  P1L = P1 + (size_t)l*3*DD;
        const __half* img = pwimg + (size_t)l*7*16384;

        qkv3<<<BN/128, 256, QKV_SMEM>>>(pxh, img + 0*16384, img + 1*16384, img + 2*16384,
                                        pq, pk, pv);
        pt_fused<<<MBIG/128, 256, FU_SMEM>>>(P1L, img + 3*16384, img + 4*16384, img + 5*16384);
        hgemm_res<<<BN/128, 256, HG_SMEM>>>(pagg, img + 6*16384, pxh, px, px);
    }

    poolmax_k<<<BB*32, DD>>>();
    cls_k<<<BB, DD>>>(Wc1, Wc2, out);
}

// round 8
// speedup vs baseline: 3.3516x; 1.0214x over previous
#include <cuda_runtime.h>
#include <cuda_fp16.h>
#include <cstdint>
#include <math.h>

// Problem constants
#define BB   8
#define NN   4096
#define KK   16
#define DD   128
#define LL   2
#define NCLS 40
#define BN   (BB*NN)          // 32768
#define MBIG (BN*KK)          // 524288

// ---------------- scratch (device globals; no allocation allowed) -----------
__device__ float  g_x[BN*DD];                 // fp32 residual stream
__device__ __half g_xh[BN*DD];                // fp16 mirror of x
__device__ __half g_q[BN*DD];
__device__ __half g_k[BN*DD];
__device__ __half g_v[BN*DD];
__device__ __half g_agg[BN*DD];
__device__ int    g_idx[MBIG];
__device__ float  g_rel[MBIG*3];
__device__ float  g_pmax[BB*32*DD];
__device__ __half g_wimg[14*DD*DD];           // fp16 weight images, [n][k] per slot

// ---------------- helpers ----------------------------------------------------
__device__ __forceinline__ uint32_t h2u(__half2 h) { return *(uint32_t*)&h; }
__device__ __forceinline__ uint32_t smem_u32(const void* p) {
    uint32_t a;
    asm("{ .reg .u64 t; cvta.to.shared.u64 t, %1; cvt.u32.u64 %0, t; }" : "=r"(a) : "l"(p));
    return a;
}
__device__ __forceinline__ void cpa16(uint32_t dst, const void* src) {
    asm volatile("cp.async.ca.shared.global [%0], [%1], 16;" :: "r"(dst), "l"(src));
}
__device__ __forceinline__ void cpa_commit() {
    asm volatile("cp.async.commit_group;" ::: "memory");
}
template<int N> __device__ __forceinline__ void cpa_wait() {
    asm volatile("cp.async.wait_group %0;" :: "n"(N) : "memory");
}
__device__ __forceinline__ void mma16(float* d, const uint32_t* a, const uint32_t* b) {
    asm volatile(
        "mma.sync.aligned.m16n8k16.row.col.f32.f16.f16.f32 "
        "{%0,%1,%2,%3}, {%4,%5,%6,%7}, {%8,%9}, {%0,%1,%2,%3};"
        : "+f"(d[0]), "+f"(d[1]), "+f"(d[2]), "+f"(d[3])
        : "r"(a[0]), "r"(a[1]), "r"(a[2]), "r"(a[3]), "r"(b[0]), "r"(b[1]));
}
__device__ __forceinline__ void ldmx4(uint32_t* r, uint32_t addr) {
    asm volatile("ldmatrix.sync.aligned.m8n8.x4.shared.b16 {%0,%1,%2,%3}, [%4];"
                 : "=r"(r[0]), "=r"(r[1]), "=r"(r[2]), "=r"(r[3]) : "r"(addr));
}

// MMA over one 64-half K chunk using ldmatrix.
__device__ __forceinline__ void mma_chunk16(uint32_t Abase, int sA, int kb,
                                            uint32_t Bbase,
                                            int r0, int c0, int lane,
                                            float acc[4][4][4]) {
    int l7 = lane & 7;
    uint32_t rowA = (uint32_t)(r0 + l7 + ((lane >> 3) & 1) * 8);
    uint32_t colA = (uint32_t)((lane >> 4) * 4);
    uint32_t aAddr = Abase + (rowA * (uint32_t)sA + (uint32_t)kb + colA) * 4u;
    uint32_t rowB = (uint32_t)(c0 + l7 + (lane >> 4) * 8);
    uint32_t colB = (uint32_t)(((lane >> 3) & 1) * 4);
    uint32_t bAddr0 = Bbase + (rowB * 36u + colB) * 4u;
    uint32_t bAddr1 = bAddr0 + 16u * 36u * 4u;
    uint32_t aStepM = (uint32_t)(16 * sA * 4);

#pragma unroll
    for (int ks = 0; ks < 4; ks++) {
        uint32_t af[4][4], bf[2][4];
#pragma unroll
        for (int mf = 0; mf < 4; mf++)
            ldmx4(af[mf], aAddr + (uint32_t)mf * aStepM + (uint32_t)(ks * 32));
        ldmx4(bf[0], bAddr0 + (uint32_t)(ks * 32));
        ldmx4(bf[1], bAddr1 + (uint32_t)(ks * 32));
#pragma unroll
        for (int mf = 0; mf < 4; mf++) {
            mma16(acc[mf][0], af[mf], &bf[0][0]);
            mma16(acc[mf][1], af[mf], &bf[0][2]);
            mma16(acc[mf][2], af[mf], &bf[1][0]);
            mma16(acc[mf][3], af[mf], &bf[1][2]);
        }
    }
}

// B stage loader: Bimg [n=128][k=128] fp16, chunk k0 (halves), stage stride 36 b32
__device__ __forceinline__ void loadB(uint32_t bsm, const __half* __restrict__ Bimg,
                                      int k0, int t) {
#pragma unroll
    for (int i = 0; i < 4; i++) {
        int idx = t + i*256;
        int n = idx >> 3, seg = idx & 7;
        cpa16(bsm + (uint32_t)(n*144 + seg*16), Bimg + (size_t)n*128 + k0 + seg*8);
    }
}
// A stage loader from fp16 global [m][128]
__device__ __forceinline__ void loadA(uint32_t asmb, const __half* __restrict__ A,
                                      int mBase, int k0, int t) {
#pragma unroll
    for (int i = 0; i < 4; i++) {
        int idx = t + i*256;
        int row = idx >> 3, seg = idx & 7;
        cpa16(asmb + (uint32_t)(row*144 + seg*16), A + (size_t)(mBase+row)*128 + k0 + seg*8);
    }
}

// ---------------- weight image prep: 14 slots in one launch ------------------
__global__ void prep_all(const float* __restrict__ Wq, const float* __restrict__ Wk,
                         const float* __restrict__ Wv, const float* __restrict__ P2,
                         const float* __restrict__ G1, const float* __restrict__ G2,
                         const float* __restrict__ Wo, __half* __restrict__ dst) {
    int slot = blockIdx.y;
    int l = slot / 7, w = slot % 7;
    const float* src;
    switch (w) {
        case 0: src = Wq; break;  case 1: src = Wk; break;
        case 2: src = Wv; break;  case 3: src = P2; break;
        case 4: src = G1; break;  case 5: src = G2; break;
        default: src = Wo; break;
    }
    src += (size_t)l*DD*DD;
    int n = blockIdx.x, k = threadIdx.x;
    dst[(size_t)slot*16384 + n*128 + k] = __float2half(src[k*128 + n]);
}

// ======================= fused q/k/v GEMM: one A tile, 3 weights ============
#define QKV_SMEM (6*4608*4)
__global__ __launch_bounds__(256, 2) void qkv3(const __half* __restrict__ A,
                                               const __half* __restrict__ B0,
                                               const __half* __restrict__ B1,
                                               const __half* __restrict__ B2,
                                               __half* __restrict__ O0,
                                               __half* __restrict__ O1,
                                               __half* __restrict__ O2) {
    extern __shared__ float sm[];
    uint32_t* Ast[2] = { (uint32_t*)sm, (uint32_t*)sm + 4608 };
    uint32_t* Bst[2] = { (uint32_t*)sm + 9216, (uint32_t*)sm + 13824 };
    int t = threadIdx.x;
    int mBase = blockIdx.x * 128;
    int lane = t & 31, wid = t >> 5;
    int r0 = (wid & 1) * 64, c0 = (wid >> 1) * 32;
    int ar = lane >> 2, ak = lane & 3;

    const __half* Bimg[3] = { B0, B1, B2 };
    __half* Out[3] = { O0, O1, O2 };
    uint32_t uA0 = smem_u32(Ast[0]), uA1 = smem_u32(Ast[1]);
    uint32_t uB0 = smem_u32(Bst[0]), uB1 = smem_u32(Bst[1]);

    loadA(uA0, A, mBase, 0, t);
    loadA(uA1, A, mBase, 64, t);
    loadB(uB0, B0, 0, t);
    cpa_commit();
    loadB(uB1, B0, 64, t);
    cpa_commit();

#pragma unroll
    for (int w = 0; w < 3; w++) {
        float acc[4][4][4] = {};
        cpa_wait<1>(); __syncthreads();
        mma_chunk16(uA0, 36, 0, uB0, r0, c0, lane, acc);
        __syncthreads();
        if (w < 2) { loadB(uB0, Bimg[w+1], 0, t); cpa_commit(); }
        if (w < 2) cpa_wait<1>(); else cpa_wait<0>();
        __syncthreads();
        mma_chunk16(uA1, 36, 0, uB1, r0, c0, lane, acc);
        __syncthreads();
        if (w < 2) { loadB(uB1, Bimg[w+1], 64, t); cpa_commit(); }
        __half* C = Out[w];
#pragma unroll
        for (int mf = 0; mf < 4; mf++)
#pragma unroll
        for (int nf = 0; nf < 4; nf++) {
            int r = mBase + r0 + mf*16 + ar;
            int c = c0 + nf*8 + 2*ak;
            *(__half2*)(C + (size_t)r*128 + c) =
                __floats2half2_rn(acc[mf][nf][0], acc[mf][nf][1]);
            *(__half2*)(C + (size_t)(r+8)*128 + c) =
                __floats2half2_rn(acc[mf][nf][2], acc[mf][nf][3]);
        }
    }
}

// ======================= residual GEMM: Cf = Res + A@W, Ch = half(Cf) =======
#define HG_SMEM (4*4608*4)
__global__ __launch_bounds__(256, 2) void hgemm_res(const __half* __restrict__ A,
                                                    const __half* __restrict__ Bimg,
                                                    __half* __restrict__ Ch,
                                                    float* __restrict__ Cf,
                                                    const float* __restrict__ Res) {
    extern __shared__ float sm[];
    uint32_t* Ast[2] = { (uint32_t*)sm, (uint32_t*)sm + 4608 };
    uint32_t* Bst[2] = { (uint32_t*)sm + 9216, (uint32_t*)sm + 13824 };
    int t = threadIdx.x;
    int mBase = blockIdx.x * 128;
    uint32_t uA0 = smem_u32(Ast[0]), uA1 = smem_u32(Ast[1]);
    uint32_t uB0 = smem_u32(Bst[0]), uB1 = smem_u32(Bst[1]);

    loadA(uA0, A, mBase, 0, t);
    loadB(uB0, Bimg, 0, t);
    cpa_commit();
    loadA(uA1, A, mBase, 64, t);
    loadB(uB1, Bimg, 64, t);
    cpa_commit();

    int lane = t & 31, wid = t >> 5;
    int r0 = (wid & 1) * 64, c0 = (wid >> 1) * 32;
    int ar = lane >> 2, ak = lane & 3;
    float acc[4][4][4] = {};

    cpa_wait<1>(); __syncthreads();
    mma_chunk16(uA0, 36, 0, uB0, r0, c0, lane, acc);
    cpa_wait<0>(); __syncthreads();
    mma_chunk16(uA1, 36, 0, uB1, r0, c0, lane, acc);

#pragma unroll
    for (int mf = 0; mf < 4; mf++)
#pragma unroll
    for (int nf = 0; nf < 4; nf++) {
        int r = mBase + r0 + mf*16 + ar;
        int c = c0 + nf*8 + 2*ak;
        float2 v0 = make_float2(acc[mf][nf][0], acc[mf][nf][1]);
        float2 v1 = make_float2(acc[mf][nf][2], acc[mf][nf][3]);
        float2 a0 = *(const float2*)(Res + (size_t)r*128 + c);
        float2 a1 = *(const float2*)(Res + (size_t)(r+8)*128 + c);
        v0.x += a0.x; v0.y += a0.y; v1.x += a1.x; v1.y += a1.y;
        *(float2*)(Cf + (size_t)r*128 + c) = v0;
        *(float2*)(Cf + (size_t)(r+8)*128 + c) = v1;
        *(__half2*)(Ch + (size_t)r*128 + c) = __floats2half2_rn(v0.x, v0.y);
        *(__half2*)(Ch + (size_t)(r+8)*128 + c) = __floats2half2_rn(v1.x, v1.y);
    }
}

// ======== fused per-neighbor block: delta -> g -> h2 -> logits -> agg =======
// smem layout (float offsets), total 27136 floats = 108544 B -> 2 CTAs/SM:
//   DlH (half2, stride 68 b32/row)  @ 0      Ast[2] @ 8704 (Hu aliases)
//   Bst[2] @ 17920                  Ls (fp32, stride 132) @ 8704 after GEMM3
#define FU_SMEM (27136*4)
__global__ __launch_bounds__(256, 2) void pt_fused(const float* __restrict__ P1L,
                                                   const __half* __restrict__ P2img,
                                                   const __half* __restrict__ G1img,
                                                   const __half* __restrict__ G2img) {
    extern __shared__ float sm[];
    uint32_t* DlH = (uint32_t*)sm;
    uint32_t* Ast[2] = { (uint32_t*)(sm + 8704), (uint32_t*)(sm + 13312) };
    uint32_t* Bst[2] = { (uint32_t*)(sm + 17920), (uint32_t*)(sm + 22528) };
    float*    Ls = sm + 8704;

    __shared__ int   rowK[128];
    __shared__ float relS[128][3];
    __shared__ float P1s[3][128];

    int t = threadIdx.x;
    int mBase = blockIdx.x * 128;
    int lane = t & 31, wid = t >> 5;
    int r0 = (wid & 1) * 64, c0 = (wid >> 1) * 32;
    int ar = lane >> 2, ak = lane & 3;
    uint32_t uA0 = smem_u32(Ast[0]), uA1 = smem_u32(Ast[1]);
    uint32_t uB0 = smem_u32(Bst[0]), uB1 = smem_u32(Bst[1]);
    uint32_t uHu = uA0;

    if (t < 128) {
        int m = mBase + t;
        rowK[t] = ((m >> 4) >> 12) * NN + g_idx[m];
        relS[t][0] = g_rel[(size_t)m*3+0];
        relS[t][1] = g_rel[(size_t)m*3+1];
        relS[t][2] = g_rel[(size_t)m*3+2];
    }
    for (int i = t; i < 384; i += 256) P1s[i/128][i%128] = P1L[i];
    __syncthreads();

    float acc[4][4][4] = {};

    // ================= GEMM1: delta = relu(rel@P1) @ P2 -> DlH ==============
    {
        loadB(uB0, P2img, 0, t);  cpa_commit();
        loadB(uB1, P2img, 64, t); cpa_commit();
#pragma unroll
        for (int st = 0; st < 2; st++) {
            int k0 = st*64;
#pragma unroll
            for (int i = 0; i < 16; i++) {
                int idx = t + i*256;
                int row = idx >> 5, j = idx & 31;
                int c = k0 + 2*j;
                float a0 = relS[row][0], a1 = relS[row][1], a2 = relS[row][2];
                float v0 = fmaxf(a0*P1s[0][c]   + a1*P1s[1][c]   + a2*P1s[2][c],   0.f);
                float v1 = fmaxf(a0*P1s[0][c+1] + a1*P1s[1][c+1] + a2*P1s[2][c+1], 0.f);
                Ast[st][row*36 + j] = h2u(__floats2half2_rn(v0, v1));
            }
        }
        cpa_wait<1>(); __syncthreads();
        mma_chunk16(uA0, 36, 0, uB0, r0, c0, lane, acc);
        cpa_wait<0>(); __syncthreads();
        mma_chunk16(uA1, 36, 0, uB1, r0, c0, lane, acc);
        __syncthreads();
#pragma unroll
        for (int mf = 0; mf < 4; mf++)
#pragma unroll
        for (int nf = 0; nf < 4; nf++) {
            int r = r0 + mf*16 + ar;
            int cb = (c0 + nf*8) >> 1;
            DlH[r*68 + cb + ak] = h2u(__floats2half2_rn(acc[mf][nf][0], acc[mf][nf][1]));
            DlH[(r+8)*68 + cb + ak] = h2u(__floats2half2_rn(acc[mf][nf][2], acc[mf][nf][3]));
            acc[mf][nf][0] = acc[mf][nf][1] = acc[mf][nf][2] = acc[mf][nf][3] = 0.f;
        }
        __syncthreads();
    }

    // ================= GEMM2: h2 = relu((q - k_g + delta) @ G1) -> Hu =======
    // A-build vectorized: thread (row = t>>1, ch = t&1) handles 64 halves via
    // 8 uint4 loads each of q, k(gathered), delta; fp16 arithmetic.
    {
        loadB(uB0, G1img, 0, t);  cpa_commit();
        loadB(uB1, G1img, 64, t); cpa_commit();
        {
            int row = t >> 1, ch = t & 1;
            int bn = (mBase + row) >> 4;
            const uint4* qv = (const uint4*)(g_q + (size_t)bn*128 + ch*64);
            const uint4* kv = (const uint4*)(g_k + (size_t)rowK[row]*128 + ch*64);
            const uint4* dv = (const uint4*)((const __half*)DlH + row*136 + ch*64);
            uint32_t* dst = Ast[ch] + row*36;
#pragma unroll
            for (int i = 0; i < 8; i++) {
                uint4 q4 = qv[i], k4 = kv[i], d4 = dv[i];
                uint4 o;
                o.x = h2u(__hadd2(__hsub2(*(__half2*)&q4.x, *(__half2*)&k4.x), *(__half2*)&d4.x));
                o.y = h2u(__hadd2(__hsub2(*(__half2*)&q4.y, *(__half2*)&k4.y), *(__half2*)&d4.y));
                o.z = h2u(__hadd2(__hsub2(*(__half2*)&q4.z, *(__half2*)&k4.z), *(__half2*)&d4.z));
                o.w = h2u(__hadd2(__hsub2(*(__half2*)&q4.w, *(__half2*)&k4.w), *(__half2*)&d4.w));
                *(uint4*)(dst + i*4) = o;
            }
        }
        cpa_wait<1>(); __syncthreads();
        mma_chunk16(uA0, 36, 0, uB0, r0, c0, lane, acc);
        cpa_wait<0>(); __syncthreads();
        mma_chunk16(uA1, 36, 0, uB1, r0, c0, lane, acc);
        __syncthreads();
        uint32_t* Hu = (uint32_t*)Ast[0];
#pragma unroll
        for (int mf = 0; mf < 4; mf++)
#pragma unroll
        for (int nf = 0; nf < 4; nf++) {
            int r = r0 + mf*16 + ar;
            int cb = (c0 + nf*8) >> 1;
            Hu[r*68 + cb + ak] = h2u(__floats2half2_rn(
                fmaxf(acc[mf][nf][0], 0.f), fmaxf(acc[mf][nf][1], 0.f)));
            Hu[(r+8)*68 + cb + ak] = h2u(__floats2half2_rn(
                fmaxf(acc[mf][nf][2], 0.f), fmaxf(acc[mf][nf][3], 0.f)));
            acc[mf][nf][0] = acc[mf][nf][1] = acc[mf][nf][2] = acc[mf][nf][3] = 0.f;
        }
        __syncthreads();
    }

    // ================= GEMM3: logits = h2 @ G2 ==============================
    {
        loadB(uB0, G2img, 0, t);  cpa_commit();
        loadB(uB1, G2img, 64, t); cpa_commit();
        cpa_wait<1>(); __syncthreads();
        mma_chunk16(uHu, 68, 0,  uB0, r0, c0, lane, acc);
        cpa_wait<0>(); __syncthreads();
        mma_chunk16(uHu, 68, 32, uB1, r0, c0, lane, acc);
        __syncthreads();
#pragma unroll
        for (int mf = 0; mf < 4; mf++)
#pragma unroll
        for (int nf = 0; nf < 4; nf++) {
            int r = r0 + mf*16 + ar;
            int c = c0 + nf*8 + 2*ak;
            Ls[r*132 + c]       = acc[mf][nf][0];
            Ls[r*132 + c+1]     = acc[mf][nf][1];
            Ls[(r+8)*132 + c]   = acc[mf][nf][2];
            Ls[(r+8)*132 + c+1] = acc[mf][nf][3];
        }
        __syncthreads();
    }

    // ================= softmax over K + aggregate (2 dims/thread) ===========
    const __half* DlHh = (const __half*)DlH;
    for (int it = t; it < 512; it += 256) {
        int p = it >> 6, dd = (it & 63) * 2;
        float2 lo[KK];
        float mx0 = -3.4e38f, mx1 = -3.4e38f;
#pragma unroll
        for (int k = 0; k < KK; k++) {
            lo[k].x = Ls[(p*16 + k)*132 + dd];
            lo[k].y = Ls[(p*16 + k)*132 + dd + 1];
            mx0 = fmaxf(mx0, lo[k].x);
            mx1 = fmaxf(mx1, lo[k].y);
        }
        float s0 = 0.f, s1 = 0.f;
#pragma unroll
        for (int k = 0; k < KK; k++) {
            lo[k].x = expf(lo[k].x - mx0); s0 += lo[k].x;
            lo[k].y = expf(lo[k].y - mx1); s1 += lo[k].y;
        }
        float i0 = 1.f / s0, i1 = 1.f / s1;
        float a0 = 0.f, a1 = 0.f;
#pragma unroll
        for (int k = 0; k < KK; k++) {
            __half2 vj = *(const __half2*)(g_v + (size_t)rowK[p*16+k]*128 + dd);
            __half2 dl = *(const __half2*)(DlHh + (p*16 + k)*136 + dd);
            a0 += lo[k].x * i0 * (__half2float(vj.x) + __half2float(dl.x));
            a1 += lo[k].y * i1 * (__half2float(vj.y) + __half2float(dl.y));
        }
        *(__half2*)(g_agg + (size_t)((mBase >> 4) + p)*128 + dd) = __floats2half2_rn(a0, a1);
    }
}

// ---------------- embedding: x = relu(features @ W_embed) -------------------
__global__ void embed_k(const float* __restrict__ f, const float* __restrict__ W) {
    int m = blockIdx.x;
    int d = threadIdx.x;
    float f0 = f[m*3+0], f1 = f[m*3+1], f2 = f[m*3+2];
    float v = fmaxf(f0*W[d] + f1*W[DD+d] + f2*W[2*DD+d], 0.f);
    g_x[m*DD + d] = v;
    g_xh[m*DD + d] = __float2half(v);
}

// ---------------- kNN (top-16 smallest d2, incl self) + rel -----------------
#define TJ 1024
__global__ __launch_bounds__(256) void knn_k(const float* __restrict__ pos) {
    int b = blockIdx.y;
    int i = blockIdx.x*256 + threadIdx.x;
    const float* pb = pos + (size_t)b*NN*3;
    float px = pb[i*3+0], py = pb[i*3+1], pz = pb[i*3+2];
    float sqi = px*px + py*py + pz*pz;

    float bd[KK]; int bi[KK];
#pragma unroll
    for (int t = 0; t < KK; t++) { bd[t] = 3.4e38f; bi[t] = -1; }
    float worst = 3.4e38f; int wslot = 0;

    __shared__ float sp[TJ*3];
    __shared__ float ssq[TJ];

    for (int j0 = 0; j0 < NN; j0 += TJ) {
        for (int t = threadIdx.x; t < TJ; t += 256) {
            float a = pb[(j0+t)*3+0];
            float c1 = pb[(j0+t)*3+1];
            float c2 = pb[(j0+t)*3+2];
            sp[t*3+0] = a; sp[t*3+1] = c1; sp[t*3+2] = c2;
            ssq[t] = a*a + c1*c1 + c2*c2;
        }
        __syncthreads();
        for (int jj = 0; jj < TJ; jj++) {
            float dot = px*sp[jj*3] + py*sp[jj*3+1] + pz*sp[jj*3+2];
            float d2 = sqi + ssq[jj] - 2.0f*dot;
            if (d2 < worst) {
                bd[wslot] = d2; bi[wslot] = j0 + jj;
                worst = bd[0]; wslot = 0;
#pragma unroll
                for (int t = 1; t < KK; t++)
                    if (bd[t] > worst) { worst = bd[t]; wslot = t; }
            }
        }
        __syncthreads();
    }
    int base = (b*NN + i)*KK;
#pragma unroll
    for (int t = 0; t < KK; t++) {
        int j = bi[t];
        g_idx[base + t] = j;
        g_rel[(size_t)(base+t)*3+0] = px - pb[j*3+0];
        g_rel[(size_t)(base+t)*3+1] = py - pb[j*3+1];
        g_rel[(size_t)(base+t)*3+2] = pz - pb[j*3+2];
    }
}

// ---------------- global max pool (partial) ---------------------------------
__global__ void poolmax_k() {
    int b  = blockIdx.x >> 5;
    int ch = blockIdx.x & 31;
    int d  = threadIdx.x;
    float m = -3.4e38f;
    for (int n = ch*128; n < ch*128 + 128; n++)
        m = fmaxf(m, g_x[((size_t)b*NN + n)*DD + d]);
    g_pmax[(size_t)blockIdx.x*DD + d] = m;
}

// ---------------- classifier head -------------------------------------------
__global__ void cls_k(const float* __restrict__ Wc1, const float* __restrict__ Wc2,
                      float* __restrict__ out) {
    int b = blockIdx.x;
    int d = threadIdx.x;
    __shared__ float pooled[DD];
    __shared__ float h[DD];
    float m = -3.4e38f;
    for (int ch = 0; ch < 32; ch++)
        m = fmaxf(m, g_pmax[((size_t)b*32 + ch)*DD + d]);
    pooled[d] = m;
    __syncthreads();
    float acc = 0.f;
    for (int c = 0; c < DD; c++) acc += pooled[c]*Wc1[c*DD + d];
    h[d] = fmaxf(acc, 0.f);
    __syncthreads();
    if (d < NCLS) {
        float o = 0.f;
        for (int c = 0; c < DD; c++) o += h[c]*Wc2[c*NCLS + d];
        out[b*NCLS + d] = o;
    }
}

// ---------------- launch -----------------------------------------------------
extern "C" void kernel_launch(void* const* d_in, const int* in_sizes, int n_in,
                              void* d_out, int out_size) {
    const float* features = (const float*)d_in[0];
    const float* pos      = (const float*)d_in[1];
    const float* W_embed  = (const float*)d_in[2];
    const float* Wq       = (const float*)d_in[3];
    const float* Wk       = (const float*)d_in[4];
    const float* Wv       = (const float*)d_in[5];
    const float* P1       = (const float*)d_in[6];
    const float* P2       = (const float*)d_in[7];
    const float* G1       = (const float*)d_in[8];
    const float* G2       = (const float*)d_in[9];
    const float* Wo       = (const float*)d_in[10];
    const float* Wc1      = (const float*)d_in[11];
    const float* Wc2      = (const float*)d_in[12];
    float* out = (float*)d_out;

    static float  *px = nullptr;
    static __half *pxh=nullptr, *pq=nullptr, *pk=nullptr, *pv=nullptr,
                  *pagg=nullptr, *pwimg=nullptr;
    if (!px) {
        cudaGetSymbolAddress((void**)&px,   g_x);
        cudaGetSymbolAddress((void**)&pxh,  g_xh);
        cudaGetSymbolAddress((void**)&pq,   g_q);
        cudaGetSymbolAddress((void**)&pk,   g_k);
        cudaGetSymbolAddress((void**)&pv,   g_v);
        cudaGetSymbolAddress((void**)&pagg, g_agg);
        cudaGetSymbolAddress((void**)&pwimg,g_wimg);
        cudaFuncSetAttribute(qkv3,      cudaFuncAttributeMaxDynamicSharedMemorySize, QKV_SMEM);
        cudaFuncSetAttribute(hgemm_res, cudaFuncAttributeMaxDynamicSharedMemorySize, HG_SMEM);
        cudaFuncSetAttribute(pt_fused,  cudaFuncAttributeMaxDynamicSharedMemorySize, FU_SMEM);
    }

    prep_all<<<dim3(128,14), 128>>>(Wq, Wk, Wv, P2, G1, G2, Wo, pwimg);
    embed_k<<<BN, DD>>>(features, W_embed);
    knn_k<<<dim3(NN/256, BB), 256>>>(pos);

    for (int l = 0; l < LL; l++) {
        const float*  P1L = P1 + (size_t)l*3*DD;
        const __half* img = pwimg + (size_t)l*7*16384;

        qkv3<<<BN/128, 256, QKV_SMEM>>>(pxh, img + 0*16384, img + 1*16384, img + 2*16384,
                                        pq, pk, pv);
        pt_fused<<<MBIG/128, 256, FU_SMEM>>>(P1L, img + 3*16384, img + 4*16384, img + 5*16384);
        hgemm_res<<<BN/128, 256, HG_SMEM>>>(pagg, img + 6*16384, pxh, px, px);
    }

    poolmax_k<<<BB*32, DD>>>();
    cls_k<<<BB, DD>>>(Wc1, Wc2, out);
}

// round 9
// speedup vs baseline: 3.3603x; 1.0026x over previous
#include <cuda_runtime.h>
#include <cuda_fp16.h>
#include <cstdint>
#include <math.h>

// Problem constants
#define BB   8
#define NN   4096
#define KK   16
#define DD   128
#define LL   2
#define NCLS 40
#define BN   (BB*NN)          // 32768
#define MBIG (BN*KK)          // 524288

// ---------------- scratch (device globals; no allocation allowed) -----------
__device__ float  g_x[BN*DD];                 // fp32 residual stream
__device__ __half g_xh[BN*DD];                // fp16 mirror of x
__device__ __half g_qg[BN*DD];                // x @ (Wq G1)
__device__ __half g_kg[BN*DD];                // x @ (Wk G1)
__device__ __half g_v[BN*DD];
__device__ __half g_agg[BN*DD];
__device__ int    g_idx[MBIG];
__device__ float  g_rel[MBIG*3];
__device__ float  g_pmax[BB*32*DD];
// per-layer slots: 0:Wv 1:WqG1 2:WkG1 3:P2 4:P2G1 5:G2 6:Wo  (fp16 [n][k])
__device__ __half g_wimg[14*DD*DD];

// ---------------- helpers ----------------------------------------------------
__device__ __forceinline__ uint32_t h2u(__half2 h) { return *(uint32_t*)&h; }
__device__ __forceinline__ uint32_t smem_u32(const void* p) {
    uint32_t a;
    asm("{ .reg .u64 t; cvta.to.shared.u64 t, %1; cvt.u32.u64 %0, t; }" : "=r"(a) : "l"(p));
    return a;
}
__device__ __forceinline__ void cpa16(uint32_t dst, const void* src) {
    asm volatile("cp.async.ca.shared.global [%0], [%1], 16;" :: "r"(dst), "l"(src));
}
__device__ __forceinline__ void cpa_commit() {
    asm volatile("cp.async.commit_group;" ::: "memory");
}
template<int N> __device__ __forceinline__ void cpa_wait() {
    asm volatile("cp.async.wait_group %0;" :: "n"(N) : "memory");
}
__device__ __forceinline__ void mma16(float* d, const uint32_t* a, const uint32_t* b) {
    asm volatile(
        "mma.sync.aligned.m16n8k16.row.col.f32.f16.f16.f32 "
        "{%0,%1,%2,%3}, {%4,%5,%6,%7}, {%8,%9}, {%0,%1,%2,%3};"
        : "+f"(d[0]), "+f"(d[1]), "+f"(d[2]), "+f"(d[3])
        : "r"(a[0]), "r"(a[1]), "r"(a[2]), "r"(a[3]), "r"(b[0]), "r"(b[1]));
}
__device__ __forceinline__ void ldmx4(uint32_t* r, uint32_t addr) {
    asm volatile("ldmatrix.sync.aligned.m8n8.x4.shared.b16 {%0,%1,%2,%3}, [%4];"
                 : "=r"(r[0]), "=r"(r[1]), "=r"(r[2]), "=r"(r[3]) : "r"(addr));
}

// MMA over one 64-half K chunk using ldmatrix.
__device__ __forceinline__ void mma_chunk16(uint32_t Abase, int sA, int kb,
                                            uint32_t Bbase,
                                            int r0, int c0, int lane,
                                            float acc[4][4][4]) {
    int l7 = lane & 7;
    uint32_t rowA = (uint32_t)(r0 + l7 + ((lane >> 3) & 1) * 8);
    uint32_t colA = (uint32_t)((lane >> 4) * 4);
    uint32_t aAddr = Abase + (rowA * (uint32_t)sA + (uint32_t)kb + colA) * 4u;
    uint32_t rowB = (uint32_t)(c0 + l7 + (lane >> 4) * 8);
    uint32_t colB = (uint32_t)(((lane >> 3) & 1) * 4);
    uint32_t bAddr0 = Bbase + (rowB * 36u + colB) * 4u;
    uint32_t bAddr1 = bAddr0 + 16u * 36u * 4u;
    uint32_t aStepM = (uint32_t)(16 * sA * 4);

#pragma unroll
    for (int ks = 0; ks < 4; ks++) {
        uint32_t af[4][4], bf[2][4];
#pragma unroll
        for (int mf = 0; mf < 4; mf++)
            ldmx4(af[mf], aAddr + (uint32_t)mf * aStepM + (uint32_t)(ks * 32));
        ldmx4(bf[0], bAddr0 + (uint32_t)(ks * 32));
        ldmx4(bf[1], bAddr1 + (uint32_t)(ks * 32));
#pragma unroll
        for (int mf = 0; mf < 4; mf++) {
            mma16(acc[mf][0], af[mf], &bf[0][0]);
            mma16(acc[mf][1], af[mf], &bf[0][2]);
            mma16(acc[mf][2], af[mf], &bf[1][0]);
            mma16(acc[mf][3], af[mf], &bf[1][2]);
        }
    }
}

// B stage loader: Bimg [n=128][k=128] fp16, chunk k0 (halves), stage stride 36 b32
__device__ __forceinline__ void loadB(uint32_t bsm, const __half* __restrict__ Bimg,
                                      int k0, int t) {
#pragma unroll
    for (int i = 0; i < 4; i++) {
        int idx = t + i*256;
        int n = idx >> 3, seg = idx & 7;
        cpa16(bsm + (uint32_t)(n*144 + seg*16), Bimg + (size_t)n*128 + k0 + seg*8);
    }
}
// A stage loader from fp16 global [m][128]
__device__ __forceinline__ void loadA(uint32_t asmb, const __half* __restrict__ A,
                                      int mBase, int k0, int t) {
#pragma unroll
    for (int i = 0; i < 4; i++) {
        int idx = t + i*256;
        int row = idx >> 3, seg = idx & 7;
        cpa16(asmb + (uint32_t)(row*144 + seg*16), A + (size_t)(mBase+row)*128 + k0 + seg*8);
    }
}

// ---------------- weight image prep (straight transposes) --------------------
__global__ void prep_all(const float* __restrict__ Wv, const float* __restrict__ P2,
                         const float* __restrict__ G2, const float* __restrict__ Wo,
                         __half* __restrict__ dst) {
    int y = blockIdx.y;                  // 0..4*LL-1
    int l = y >> 2, w = y & 3;
    const float* src;
    int slot;
    switch (w) {
        case 0: src = Wv; slot = 0; break;
        case 1: src = P2; slot = 3; break;
        case 2: src = G2; slot = 5; break;
        default: src = Wo; slot = 6; break;
    }
    src += (size_t)l*DD*DD;
    int n = blockIdx.x, k = threadIdx.x;
    dst[(size_t)(l*7 + slot)*16384 + n*128 + k] = __float2half(src[k*128 + n]);
}

// ---------------- composite weight prep: (A @ G1) images ---------------------
// y -> (l, w): w=0: Wq@G1 -> slot1 ; w=1: Wk@G1 -> slot2 ; w=2: P2@G1 -> slot4
__global__ void prep_combo(const float* __restrict__ Wq, const float* __restrict__ Wk,
                           const float* __restrict__ P2, const float* __restrict__ G1,
                           __half* __restrict__ dst) {
    int n = blockIdx.x;
    int y = blockIdx.y;
    int l = y / 3, w = y % 3;
    const float* A = (w == 0 ? Wq : (w == 1 ? Wk : P2)) + (size_t)l*DD*DD;
    const float* B = G1 + (size_t)l*DD*DD;
    __shared__ float Bcol[DD];
    int k = threadIdx.x;
    Bcol[k] = B[k*DD + n];
    __syncthreads();
    float acc = 0.f;
#pragma unroll 8
    for (int c = 0; c < DD; c++) acc += A[k*DD + c] * Bcol[c];
    int slot = (w == 0 ? 1 : (w == 1 ? 2 : 4));
    dst[(size_t)(l*7 + slot)*16384 + n*DD + k] = __float2half(acc);
}

// ======================= fused GEMM: one A tile, 3 weights ==================
#define QKV_SMEM (6*4608*4)
__global__ __launch_bounds__(256, 2) void qkv3(const __half* __restrict__ A,
                                               const __half* __restrict__ B0,
                                               const __half* __restrict__ B1,
                                               const __half* __restrict__ B2,
                                               __half* __restrict__ O0,
                                               __half* __restrict__ O1,
                                               __half* __restrict__ O2) {
    extern __shared__ float sm[];
    uint32_t* Ast[2] = { (uint32_t*)sm, (uint32_t*)sm + 4608 };
    uint32_t* Bst[2] = { (uint32_t*)sm + 9216, (uint32_t*)sm + 13824 };
    int t = threadIdx.x;
    int mBase = blockIdx.x * 128;
    int lane = t & 31, wid = t >> 5;
    int r0 = (wid & 1) * 64, c0 = (wid >> 1) * 32;
    int ar = lane >> 2, ak = lane & 3;

    const __half* Bimg[3] = { B0, B1, B2 };
    __half* Out[3] = { O0, O1, O2 };
    uint32_t uA0 = smem_u32(Ast[0]), uA1 = smem_u32(Ast[1]);
    uint32_t uB0 = smem_u32(Bst[0]), uB1 = smem_u32(Bst[1]);

    loadA(uA0, A, mBase, 0, t);
    loadA(uA1, A, mBase, 64, t);
    loadB(uB0, B0, 0, t);
    cpa_commit();
    loadB(uB1, B0, 64, t);
    cpa_commit();

#pragma unroll
    for (int w = 0; w < 3; w++) {
        float acc[4][4][4] = {};
        cpa_wait<1>(); __syncthreads();
        mma_chunk16(uA0, 36, 0, uB0, r0, c0, lane, acc);
        __syncthreads();
        if (w < 2) { loadB(uB0, Bimg[w+1], 0, t); cpa_commit(); }
        if (w < 2) cpa_wait<1>(); else cpa_wait<0>();
        __syncthreads();
        mma_chunk16(uA1, 36, 0, uB1, r0, c0, lane, acc);
        __syncthreads();
        if (w < 2) { loadB(uB1, Bimg[w+1], 64, t); cpa_commit(); }
        __half* C = Out[w];
#pragma unroll
        for (int mf = 0; mf < 4; mf++)
#pragma unroll
        for (int nf = 0; nf < 4; nf++) {
            int r = mBase + r0 + mf*16 + ar;
            int c = c0 + nf*8 + 2*ak;
            *(__half2*)(C + (size_t)r*128 + c) =
                __floats2half2_rn(acc[mf][nf][0], acc[mf][nf][1]);
            *(__half2*)(C + (size_t)(r+8)*128 + c) =
                __floats2half2_rn(acc[mf][nf][2], acc[mf][nf][3]);
        }
    }
}

// ======================= residual GEMM: Cf = Res + A@W, Ch = half(Cf) =======
#define HG_SMEM (4*4608*4)
__global__ __launch_bounds__(256, 2) void hgemm_res(const __half* __restrict__ A,
                                                    const __half* __restrict__ Bimg,
                                                    __half* __restrict__ Ch,
                                                    float* __restrict__ Cf,
                                                    const float* __restrict__ Res) {
    extern __shared__ float sm[];
    uint32_t* Ast[2] = { (uint32_t*)sm, (uint32_t*)sm + 4608 };
    uint32_t* Bst[2] = { (uint32_t*)sm + 9216, (uint32_t*)sm + 13824 };
    int t = threadIdx.x;
    int mBase = blockIdx.x * 128;
    uint32_t uA0 = smem_u32(Ast[0]), uA1 = smem_u32(Ast[1]);
    uint32_t uB0 = smem_u32(Bst[0]), uB1 = smem_u32(Bst[1]);

    loadA(uA0, A, mBase, 0, t);
    loadB(uB0, Bimg, 0, t);
    cpa_commit();
    loadA(uA1, A, mBase, 64, t);
    loadB(uB1, Bimg, 64, t);
    cpa_commit();

    int lane = t & 31, wid = t >> 5;
    int r0 = (wid & 1) * 64, c0 = (wid >> 1) * 32;
    int ar = lane >> 2, ak = lane & 3;
    float acc[4][4][4] = {};

    cpa_wait<1>(); __syncthreads();
    mma_chunk16(uA0, 36, 0, uB0, r0, c0, lane, acc);
    cpa_wait<0>(); __syncthreads();
    mma_chunk16(uA1, 36, 0, uB1, r0, c0, lane, acc);

#pragma unroll
    for (int mf = 0; mf < 4; mf++)
#pragma unroll
    for (int nf = 0; nf < 4; nf++) {
        int r = mBase + r0 + mf*16 + ar;
        int c = c0 + nf*8 + 2*ak;
        float2 v0 = make_float2(acc[mf][nf][0], acc[mf][nf][1]);
        float2 v1 = make_float2(acc[mf][nf][2], acc[mf][nf][3]);
        float2 a0 = *(const float2*)(Res + (size_t)r*128 + c);
        float2 a1 = *(const float2*)(Res + (size_t)(r+8)*128 + c);
        v0.x += a0.x; v0.y += a0.y; v1.x += a1.x; v1.y += a1.y;
        *(float2*)(Cf + (size_t)r*128 + c) = v0;
        *(float2*)(Cf + (size_t)(r+8)*128 + c) = v1;
        *(__half2*)(Ch + (size_t)r*128 + c) = __floats2half2_rn(v0.x, v0.y);
        *(__half2*)(Ch + (size_t)(r+8)*128 + c) = __floats2half2_rn(v1.x, v1.y);
    }
}

// ======== fused per-neighbor block (linearity-restructured) =================
// A_pair = relu(rel@P1) ; delta = A_pair@P2 ; dg = A_pair@P2G1 (same A tile!);
// h2 = relu(dg + qg_i - kg_j) in epilogue ; logits = h2@G2 ; softmax ; agg.
// smem layout (float offsets), total 27136 floats = 108544 B -> 2 CTAs/SM:
//   DlH (half2, stride 68 b32/row)  @ 0      Ast[2] @ 8704 (Hu aliases)
//   Bst[2] @ 17920                  Ls (fp32, stride 132) @ 8704 after GEMM3
#define FU_SMEM (27136*4)
__global__ __launch_bounds__(256, 2) void pt_fused(const float* __restrict__ P1L,
                                                   const __half* __restrict__ P2img,
                                                   const __half* __restrict__ P21img,
                                                   const __half* __restrict__ G2img) {
    extern __shared__ float sm[];
    uint32_t* DlH = (uint32_t*)sm;
    uint32_t* Ast[2] = { (uint32_t*)(sm + 8704), (uint32_t*)(sm + 13312) };
    uint32_t* Bst[2] = { (uint32_t*)(sm + 17920), (uint32_t*)(sm + 22528) };
    float*    Ls = sm + 8704;

    __shared__ int   rowK[128];
    __shared__ float relS[128][3];
    __shared__ float P1s[3][128];

    int t = threadIdx.x;
    int mBase = blockIdx.x * 128;
    int lane = t & 31, wid = t >> 5;
    int r0 = (wid & 1) * 64, c0 = (wid >> 1) * 32;
    int ar = lane >> 2, ak = lane & 3;
    uint32_t uA0 = smem_u32(Ast[0]), uA1 = smem_u32(Ast[1]);
    uint32_t uB0 = smem_u32(Bst[0]), uB1 = smem_u32(Bst[1]);
    uint32_t uHu = uA0;

    if (t < 128) {
        int m = mBase + t;
        rowK[t] = ((m >> 4) >> 12) * NN + g_idx[m];
        relS[t][0] = g_rel[(size_t)m*3+0];
        relS[t][1] = g_rel[(size_t)m*3+1];
        relS[t][2] = g_rel[(size_t)m*3+2];
    }
    for (int i = t; i < 384; i += 256) P1s[i/128][i%128] = P1L[i];

    // B prefetch groups roll across the 3 GEMMs
    loadB(uB0, P2img, 0, t);  cpa_commit();     // g1
    loadB(uB1, P2img, 64, t); cpa_commit();     // g2
    __syncthreads();                            // relS/P1s ready

    // ---- build A_pair = relu(rel @ P1) into Ast[0..1] (used by GEMM A & B) --
#pragma unroll
    for (int st = 0; st < 2; st++) {
        int k0 = st*64;
#pragma unroll
        for (int i = 0; i < 16; i++) {
            int idx = t + i*256;
            int row = idx >> 5, j = idx & 31;
            int c = k0 + 2*j;
            float a0 = relS[row][0], a1 = relS[row][1], a2 = relS[row][2];
            float v0 = fmaxf(a0*P1s[0][c]   + a1*P1s[1][c]   + a2*P1s[2][c],   0.f);
            float v1 = fmaxf(a0*P1s[0][c+1] + a1*P1s[1][c+1] + a2*P1s[2][c+1], 0.f);
            Ast[st][row*36 + j] = h2u(__floats2half2_rn(v0, v1));
        }
    }

    float acc[4][4][4] = {};

    // ================= GEMM A: delta = A_pair @ P2 -> DlH ===================
    cpa_wait<1>(); __syncthreads();
    mma_chunk16(uA0, 36, 0, uB0, r0, c0, lane, acc);
    __syncthreads();
    loadB(uB0, P21img, 0, t); cpa_commit();     // g3
    cpa_wait<1>(); __syncthreads();
    mma_chunk16(uA1, 36, 0, uB1, r0, c0, lane, acc);
    __syncthreads();
    loadB(uB1, P21img, 64, t); cpa_commit();    // g4
#pragma unroll
    for (int mf = 0; mf < 4; mf++)
#pragma unroll
    for (int nf = 0; nf < 4; nf++) {
        int r = r0 + mf*16 + ar;
        int cb = (c0 + nf*8) >> 1;
        DlH[r*68 + cb + ak] = h2u(__floats2half2_rn(acc[mf][nf][0], acc[mf][nf][1]));
        DlH[(r+8)*68 + cb + ak] = h2u(__floats2half2_rn(acc[mf][nf][2], acc[mf][nf][3]));
        acc[mf][nf][0] = acc[mf][nf][1] = acc[mf][nf][2] = acc[mf][nf][3] = 0.f;
    }

    // ================= GEMM B: dg = A_pair @ (P2 G1); h2 in epilogue ========
    cpa_wait<1>(); __syncthreads();
    mma_chunk16(uA0, 36, 0, uB0, r0, c0, lane, acc);
    __syncthreads();
    loadB(uB0, G2img, 0, t); cpa_commit();      // g5
    cpa_wait<1>(); __syncthreads();
    mma_chunk16(uA1, 36, 0, uB1, r0, c0, lane, acc);
    __syncthreads();                            // A_pair dead; safe to write Hu
    loadB(uB1, G2img, 64, t); cpa_commit();     // g6
    {
        uint32_t* Hu = (uint32_t*)Ast[0];
#pragma unroll
        for (int mf = 0; mf < 4; mf++)
#pragma unroll
        for (int nf = 0; nf < 4; nf++) {
            int r = r0 + mf*16 + ar;
            int c = c0 + nf*8 + 2*ak;
            int bn0 = (mBase + r) >> 4, bn1 = (mBase + r + 8) >> 4;
            __half2 q0 = *(const __half2*)(g_qg + (size_t)bn0*128 + c);
            __half2 k0h = *(const __half2*)(g_kg + (size_t)rowK[r]*128 + c);
            __half2 q1 = *(const __half2*)(g_qg + (size_t)bn1*128 + c);
            __half2 k1h = *(const __half2*)(g_kg + (size_t)rowK[r+8]*128 + c);
            float h00 = fmaxf(acc[mf][nf][0] + __half2float(q0.x) - __half2float(k0h.x), 0.f);
            float h01 = fmaxf(acc[mf][nf][1] + __half2float(q0.y) - __half2float(k0h.y), 0.f);
            float h10 = fmaxf(acc[mf][nf][2] + __half2float(q1.x) - __half2float(k1h.x), 0.f);
            float h11 = fmaxf(acc[mf][nf][3] + __half2float(q1.y) - __half2float(k1h.y), 0.f);
            int cb = (c0 + nf*8) >> 1;
            Hu[r*68 + cb + ak] = h2u(__floats2half2_rn(h00, h01));
            Hu[(r+8)*68 + cb + ak] = h2u(__floats2half2_rn(h10, h11));
            acc[mf][nf][0] = acc[mf][nf][1] = acc[mf][nf][2] = acc[mf][nf][3] = 0.f;
        }
    }
    __syncthreads();                            // Hu visible to all warps

    // ================= GEMM C: logits = h2 @ G2 =============================
    cpa_wait<1>(); __syncthreads();
    mma_chunk16(uHu, 68, 0,  uB0, r0, c0, lane, acc);
    cpa_wait<0>(); __syncthreads();
    mma_chunk16(uHu, 68, 32, uB1, r0, c0, lane, acc);
    __syncthreads();                            // Hu/Bst dead -> write Ls
#pragma unroll
    for (int mf = 0; mf < 4; mf++)
#pragma unroll
    for (int nf = 0; nf < 4; nf++) {
        int r = r0 + mf*16 + ar;
        int c = c0 + nf*8 + 2*ak;
        Ls[r*132 + c]       = acc[mf][nf][0];
        Ls[r*132 + c+1]     = acc[mf][nf][1];
        Ls[(r+8)*132 + c]   = acc[mf][nf][2];
        Ls[(r+8)*132 + c+1] = acc[mf][nf][3];
    }
    __syncthreads();

    // ================= softmax over K + aggregate (2 dims/thread) ===========
    const __half* DlHh = (const __half*)DlH;
    for (int it = t; it < 512; it += 256) {
        int p = it >> 6, dd = (it & 63) * 2;
        float2 lo[KK];
        float mx0 = -3.4e38f, mx1 = -3.4e38f;
#pragma unroll
        for (int k = 0; k < KK; k++) {
            lo[k].x = Ls[(p*16 + k)*132 + dd];
            lo[k].y = Ls[(p*16 + k)*132 + dd + 1];
            mx0 = fmaxf(mx0, lo[k].x);
            mx1 = fmaxf(mx1, lo[k].y);
        }
        float s0 = 0.f, s1 = 0.f;
#pragma unroll
        for (int k = 0; k < KK; k++) {
            lo[k].x = expf(lo[k].x - mx0); s0 += lo[k].x;
            lo[k].y = expf(lo[k].y - mx1); s1 += lo[k].y;
        }
        float i0 = 1.f / s0, i1 = 1.f / s1;
        float a0 = 0.f, a1 = 0.f;
#pragma unroll
        for (int k = 0; k < KK; k++) {
            __half2 vj = *(const __half2*)(g_v + (size_t)rowK[p*16+k]*128 + dd);
            __half2 dl = *(const __half2*)(DlHh + (p*16 + k)*136 + dd);
            a0 += lo[k].x * i0 * (__half2float(vj.x) + __half2float(dl.x));
            a1 += lo[k].y * i1 * (__half2float(vj.y) + __half2float(dl.y));
        }
        *(__half2*)(g_agg + (size_t)((mBase >> 4) + p)*128 + dd) = __floats2half2_rn(a0, a1);
    }
}

// ---------------- embedding: x = relu(features @ W_embed) -------------------
__global__ void embed_k(const float* __restrict__ f, const float* __restrict__ W) {
    int m = blockIdx.x;
    int d = threadIdx.x;
    float f0 = f[m*3+0], f1 = f[m*3+1], f2 = f[m*3+2];
    float v = fmaxf(f0*W[d] + f1*W[DD+d] + f2*W[2*DD+d], 0.f);
    g_x[m*DD + d] = v;
    g_xh[m*DD + d] = __float2half(v);
}

// ---------------- kNN (top-16 smallest d2, incl self) + rel -----------------
#define TJ 1024
__global__ __launch_bounds__(256) void knn_k(const float* __restrict__ pos) {
    int b = blockIdx.y;
    int i = blockIdx.x*256 + threadIdx.x;
    const float* pb = pos + (size_t)b*NN*3;
    float px = pb[i*3+0], py = pb[i*3+1], pz = pb[i*3+2];
    float sqi = px*px + py*py + pz*pz;

    float bd[KK]; int bi[KK];
#pragma unroll
    for (int t = 0; t < KK; t++) { bd[t] = 3.4e38f; bi[t] = -1; }
    float worst = 3.4e38f; int wslot = 0;

    __shared__ float sp[TJ*3];
    __shared__ float ssq[TJ];

    for (int j0 = 0; j0 < NN; j0 += TJ) {
        for (int t = threadIdx.x; t < TJ; t += 256) {
            float a = pb[(j0+t)*3+0];
            float c1 = pb[(j0+t)*3+1];
            float c2 = pb[(j0+t)*3+2];
            sp[t*3+0] = a; sp[t*3+1] = c1; sp[t*3+2] = c2;
            ssq[t] = a*a + c1*c1 + c2*c2;
        }
        __syncthreads();
        for (int jj = 0; jj < TJ; jj++) {
            float dot = px*sp[jj*3] + py*sp[jj*3+1] + pz*sp[jj*3+2];
            float d2 = sqi + ssq[jj] - 2.0f*dot;
            if (d2 < worst) {
                bd[wslot] = d2; bi[wslot] = j0 + jj;
                worst = bd[0]; wslot = 0;
#pragma unroll
                for (int t = 1; t < KK; t++)
                    if (bd[t] > worst) { worst = bd[t]; wslot = t; }
            }
        }
        __syncthreads();
    }
    int base = (b*NN + i)*KK;
#pragma unroll
    for (int t = 0; t < KK; t++) {
        int j = bi[t];
        g_idx[base + t] = j;
        g_rel[(size_t)(base+t)*3+0] = px - pb[j*3+0];
        g_rel[(size_t)(base+t)*3+1] = py - pb[j*3+1];
        g_rel[(size_t)(base+t)*3+2] = pz - pb[j*3+2];
    }
}

// ---------------- global max pool (partial) ---------------------------------
__global__ void poolmax_k() {
    int b  = blockIdx.x >> 5;
    int ch = blockIdx.x & 31;
    int d  = threadIdx.x;
    float m = -3.4e38f;
    for (int n = ch*128; n < ch*128 + 128; n++)
        m = fmaxf(m, g_x[((size_t)b*NN + n)*DD + d]);
    g_pmax[(size_t)blockIdx.x*DD + d] = m;
}

// ---------------- classifier head -------------------------------------------
__global__ void cls_k(const float* __restrict__ Wc1, const float* __restrict__ Wc2,
                      float* __restrict__ out) {
    int b = blockIdx.x;
    int d = threadIdx.x;
    __shared__ float pooled[DD];
    __shared__ float h[DD];
    float m = -3.4e38f;
    for (int ch = 0; ch < 32; ch++)
        m = fmaxf(m, g_pmax[((size_t)b*32 + ch)*DD + d]);
    pooled[d] = m;
    __syncthreads();
    float acc = 0.f;
    for (int c = 0; c < DD; c++) acc += pooled[c]*Wc1[c*DD + d];
    h[d] = fmaxf(acc, 0.f);
    __syncthreads();
    if (d < NCLS) {
        float o = 0.f;
        for (int c = 0; c < DD; c++) o += h[c]*Wc2[c*NCLS + d];
        out[b*NCLS + d] = o;
    }
}

// ---------------- launch -----------------------------------------------------
extern "C" void kernel_launch(void* const* d_in, const int* in_sizes, int n_in,
                              void* d_out, int out_size) {
    const float* features = (const float*)d_in[0];
    const float* pos      = (const float*)d_in[1];
    const float* W_embed  = (const float*)d_in[2];
    const float* Wq       = (const float*)d_in[3];
    const float* Wk       = (const float*)d_in[4];
    const float* Wv       = (const float*)d_in[5];
    const float* P1       = (const float*)d_in[6];
    const float* P2       = (const float*)d_in[7];
    const float* G1       = (const float*)d_in[8];
    const float* G2       = (const float*)d_in[9];
    const float* Wo       = (const float*)d_in[10];
    const float* Wc1      = (const float*)d_in[11];
    const float* Wc2      = (const float*)d_in[12];
    float* out = (float*)d_out;

    static float  *px = nullptr;
    static __half *pxh=nullptr, *pqg=nullptr, *pkg=nullptr, *pv=nullptr,
                  *pagg=nullptr, *pwimg=nullptr;
    if (!px) {
        cudaGetSymbolAddress((void**)&px,   g_x);
        cudaGetSymbolAddress((void**)&pxh,  g_xh);
        cudaGetSymbolAddress((void**)&pqg,  g_qg);
        cudaGetSymbolAddress((void**)&pkg,  g_kg);
        cudaGetSymbolAddress((void**)&pv,   g_v);
        cudaGetSymbolAddress((void**)&pagg, g_agg);
        cudaGetSymbolAddress((void**)&pwimg,g_wimg);
        cudaFuncSetAttribute(qkv3,      cudaFuncAttributeMaxDynamicSharedMemorySize, QKV_SMEM);
        cudaFuncSetAttribute(hgemm_res, cudaFuncAttributeMaxDynamicSharedMemorySize, HG_SMEM);
        cudaFuncSetAttribute(pt_fused,  cudaFuncAttributeMaxDynamicSharedMemorySize, FU_SMEM);
    }

    prep_all<<<dim3(128, 4*LL), 128>>>(Wv, P2, G2, Wo, pwimg);
    prep_combo<<<dim3(128, 3*LL), 128>>>(Wq, Wk, P2, G1, pwimg);
    embed_k<<<BN, DD>>>(features, W_embed);
    knn_k<<<dim3(NN/256, BB), 256>>>(pos);

    for (int l = 0; l < LL; l++) {
        const float*  P1L = P1 + (size_t)l*3*DD;
        const __half* img = pwimg + (size_t)l*7*16384;

        qkv3<<<BN/128, 256, QKV_SMEM>>>(pxh, img + 0*16384, img + 1*16384, img + 2*16384,
                                        pv, pqg, pkg);
        pt_fused<<<MBIG/128, 256, FU_SMEM>>>(P1L, img + 3*16384, img + 4*16384, img + 5*16384);
        hgemm_res<<<BN/128, 256, HG_SMEM>>>(pagg, img + 6*16384, pxh, px, px);
    }

    poolmax_k<<<BB*32, DD>>>();
    cls_k<<<BB, DD>>>(Wc1, Wc2, out);
}